// round 3
// baseline (speedup 1.0000x reference)
#include <cuda_runtime.h>
#include <math.h>

// Problem dims
#define BB   4
#define SS   2048
#define FF   512
#define HH   8
#define DKK  64
#define DVV  64
#define FILT 512

// Scratch (allocation-free rule: __device__ globals)
__device__ float g_Q[BB*HH*SS*DKK];      // [b,h,s,dk]
__device__ float g_K[BB*HH*SS*DKK];
__device__ float g_V[BB*HH*SS*DVV];
__device__ float g_att[BB*SS*HH*DVV];    // [b,s,h*dv] concat layout

// ---------------------------------------------------------------------------
// helpers
// ---------------------------------------------------------------------------
__device__ __forceinline__ unsigned f2tf(float x) {
    unsigned r;
    asm("cvt.rna.tf32.f32 %0, %1;" : "=r"(r) : "f"(x));
    return r;
}

// exp2 on FMA pipe (no MUFU). Input y <= 0 (may be hugely negative).
__device__ __forceinline__ float exp2_fast(float y) {
    y = fmaxf(y, -126.0f);
    float t = y + 12582912.0f;                 // round-to-nearest-int magic
    float n = t - 12582912.0f;
    float f = y - n;                            // f in [-0.5, 0.5]
    float p = 0.0013333558f;
    p = fmaf(p, f, 0.0096181291f);
    p = fmaf(p, f, 0.0555041087f);
    p = fmaf(p, f, 0.2402265070f);
    p = fmaf(p, f, 0.6931471806f);
    p = fmaf(p, f, 1.0f);
    int ni = __float_as_int(t) - 0x4B400000;
    float sc = __int_as_float((ni + 127) << 23);
    return p * sc;
}

__device__ __forceinline__ void mma_tf32(float& d0, float& d1, float& d2, float& d3,
                                         unsigned a0, unsigned a1, unsigned a2, unsigned a3,
                                         unsigned b0, unsigned b1) {
    asm("mma.sync.aligned.m16n8k8.row.col.f32.tf32.tf32.f32 "
        "{%0,%1,%2,%3}, {%4,%5,%6,%7}, {%8,%9}, {%0,%1,%2,%3};"
        : "+f"(d0), "+f"(d1), "+f"(d2), "+f"(d3)
        : "r"(a0), "r"(a1), "r"(a2), "r"(a3), "r"(b0), "r"(b1));
}

// ---------------------------------------------------------------------------
// Split-tf32 GEMM (fp32 accuracy on tensor pipe):
//   out[M,N] tile 128x64 per block, 8 warps x (16 rows x 64 cols).
//   A, B split into tf32 hi+lo; compute hi*hi + hi*lo + lo*hi.
// Used for Q/K/V projections (N=64, B per head) and output GEMM.
// ---------------------------------------------------------------------------
__device__ __forceinline__ void gemm_split_tile(
    const float* __restrict__ Ab,    // A block base: rows row0.., stride FF
    const float* __restrict__ Bb,    // B base: [FF, ldb], window cols col0..
    int ldb, int col0,
    const float* __restrict__ bias,  // bias base (indexed by column window)
    float* __restrict__ Ob, int ldo) // out block base, stride ldo
{
    __shared__ float sX[128][36];
    __shared__ float sWhi[32][72];
    __shared__ float sWlo[32][72];

    const int tid  = threadIdx.x;
    const int w    = tid >> 5;
    const int lane = tid & 31;
    const int g    = lane >> 2;
    const int t    = lane & 3;

    float acc[8][4];
    #pragma unroll
    for (int nt = 0; nt < 8; nt++)
        #pragma unroll
        for (int j = 0; j < 4; j++) acc[nt][j] = 0.f;

    for (int kt = 0; kt < FF; kt += 32) {
        // stage A tile 128x32 (fp32)
        #pragma unroll
        for (int p = 0; p < 4; p++) {
            int id = tid + p * 256;
            int r  = id >> 3;
            int c4 = (id & 7) * 4;
            float4 v = *reinterpret_cast<const float4*>(Ab + (size_t)r * FF + kt + c4);
            *reinterpret_cast<float4*>(&sX[r][c4]) = v;
        }
        // stage B tile 32x64, split hi/lo
        #pragma unroll
        for (int p = 0; p < 2; p++) {
            int id = tid + p * 256;
            int r  = id >> 4;
            int c4 = (id & 15) * 4;
            float4 v = *reinterpret_cast<const float4*>(Bb + (size_t)(kt + r) * ldb + col0 + c4);
            float4 hi, lo;
            hi.x = __uint_as_float(f2tf(v.x)); lo.x = __uint_as_float(f2tf(v.x - hi.x));
            hi.y = __uint_as_float(f2tf(v.y)); lo.y = __uint_as_float(f2tf(v.y - hi.y));
            hi.z = __uint_as_float(f2tf(v.z)); lo.z = __uint_as_float(f2tf(v.z - hi.z));
            hi.w = __uint_as_float(f2tf(v.w)); lo.w = __uint_as_float(f2tf(v.w - hi.w));
            *reinterpret_cast<float4*>(&sWhi[r][c4]) = hi;
            *reinterpret_cast<float4*>(&sWlo[r][c4]) = lo;
        }
        __syncthreads();

        #pragma unroll
        for (int kk = 0; kk < 4; kk++) {
            float a0 = sX[w * 16 + g    ][kk * 8 + t    ];
            float a1 = sX[w * 16 + g + 8][kk * 8 + t    ];
            float a2 = sX[w * 16 + g    ][kk * 8 + t + 4];
            float a3 = sX[w * 16 + g + 8][kk * 8 + t + 4];
            unsigned ah0 = f2tf(a0), ah1 = f2tf(a1), ah2 = f2tf(a2), ah3 = f2tf(a3);
            unsigned al0 = f2tf(a0 - __uint_as_float(ah0));
            unsigned al1 = f2tf(a1 - __uint_as_float(ah1));
            unsigned al2 = f2tf(a2 - __uint_as_float(ah2));
            unsigned al3 = f2tf(a3 - __uint_as_float(ah3));

            #pragma unroll
            for (int nt = 0; nt < 8; nt++) {
                unsigned bh0 = __float_as_uint(sWhi[kk * 8 + t    ][nt * 8 + g]);
                unsigned bh1 = __float_as_uint(sWhi[kk * 8 + t + 4][nt * 8 + g]);
                unsigned bl0 = __float_as_uint(sWlo[kk * 8 + t    ][nt * 8 + g]);
                unsigned bl1 = __float_as_uint(sWlo[kk * 8 + t + 4][nt * 8 + g]);
                mma_tf32(acc[nt][0], acc[nt][1], acc[nt][2], acc[nt][3],
                         ah0, ah1, ah2, ah3, bh0, bh1);
                mma_tf32(acc[nt][0], acc[nt][1], acc[nt][2], acc[nt][3],
                         ah0, ah1, ah2, ah3, bl0, bl1);
                mma_tf32(acc[nt][0], acc[nt][1], acc[nt][2], acc[nt][3],
                         al0, al1, al2, al3, bh0, bh1);
            }
        }
        __syncthreads();
    }

    // epilogue: C frag (g,t) holds rows g,g+8, cols 2t,2t+1 of each 16x8 tile
    int r0 = w * 16 + g;
    #pragma unroll
    for (int nt = 0; nt < 8; nt++) {
        int c = col0 + nt * 8 + 2 * t;
        float b0 = bias[c - col0 + col0];  // bias indexed by absolute col
        float b1 = bias[c - col0 + col0 + 1];
        float2 v0 = make_float2(acc[nt][0] + b0, acc[nt][1] + b1);
        float2 v1 = make_float2(acc[nt][2] + b0, acc[nt][3] + b1);
        *reinterpret_cast<float2*>(Ob + (size_t)r0 * ldo + c) = v0;
        *reinterpret_cast<float2*>(Ob + (size_t)(r0 + 8) * ldo + c) = v1;
    }
}

// Projection: out[b,h,s,:] = X[b,s,:] @ W[h,:,:] + bias[h,:]
__global__ __launch_bounds__(256, 2) void proj_mma_kernel(
    const float* __restrict__ X,    // [B,S,F]
    const float* __restrict__ W,    // [H,F,64]
    const float* __restrict__ bias, // [H,64]
    float* __restrict__ out)        // [B,H,S,64]
{
    const int b    = blockIdx.z;
    const int h    = blockIdx.y;
    const int row0 = blockIdx.x * 128;
    gemm_split_tile(X + ((size_t)b * SS + row0) * FF,
                    W + (size_t)h * FF * DKK, DKK, 0,
                    bias + h * DKK,
                    out + (((size_t)b * HH + h) * SS + row0) * DKK, DKK);
}

// Output GEMM: out[M,512] = att[M,512] @ Wo[512,512] + bo
__global__ __launch_bounds__(256, 2) void out_mma_kernel(
    const float* __restrict__ A,
    const float* __restrict__ Wo,
    const float* __restrict__ bo,
    float* __restrict__ out)
{
    const int row0 = blockIdx.x * 128;
    const int col0 = blockIdx.y * 64;
    gemm_split_tile(A + (size_t)row0 * FF,
                    Wo, FILT, col0,
                    bo,
                    out + (size_t)row0 * FILT, FILT);
}

// ---------------------------------------------------------------------------
// Flash attention via mma.sync tf32 (tensor pipe), exp2 on FMA pipe.
// Block: 256 threads = 8 warps. Br=128 rows/block (16 rows/warp), Bc=64.
// launch_bounds(256,2) => 2 CTAs/SM to overlap tensor and softmax phases.
// ---------------------------------------------------------------------------
__global__ __launch_bounds__(256, 2) void attn_mma_kernel()
{
    const int b  = blockIdx.z;
    const int h  = blockIdx.y;
    const int q0 = blockIdx.x * 128;

    const int tid  = threadIdx.x;
    const int w    = tid >> 5;
    const int lane = tid & 31;
    const int g    = lane >> 2;
    const int t    = lane & 3;

    __shared__ float sK[64][72];
    __shared__ float sV[64][72];

    const float* Qb = g_Q + (((size_t)b * HH + h) * SS + q0 + w * 16) * DKK;
    const float* Kb = g_K + ((size_t)b * HH + h) * SS * DKK;
    const float* Vb = g_V + ((size_t)b * HH + h) * SS * DVV;

    const float QS = 0.125f * 1.4426950408889634f;  // softmax scale * log2(e)

    unsigned qa[8][4];
    #pragma unroll
    for (int kk = 0; kk < 8; kk++) {
        qa[kk][0] = f2tf(Qb[(size_t)(g    ) * DKK + kk * 8 + t    ] * QS);
        qa[kk][1] = f2tf(Qb[(size_t)(g + 8) * DKK + kk * 8 + t    ] * QS);
        qa[kk][2] = f2tf(Qb[(size_t)(g    ) * DKK + kk * 8 + t + 4] * QS);
        qa[kk][3] = f2tf(Qb[(size_t)(g + 8) * DKK + kk * 8 + t + 4] * QS);
    }

    float o[8][4];
    #pragma unroll
    for (int vt = 0; vt < 8; vt++)
        #pragma unroll
        for (int j = 0; j < 4; j++) o[vt][j] = 0.f;

    float m0 = -1e30f, m1 = -1e30f, l0 = 0.f, l1 = 0.f;

    for (int kt = 0; kt < SS; kt += 64) {
        #pragma unroll
        for (int p = 0; p < 4; p++) {
            int f  = tid + p * 256;
            int r  = f >> 4;
            int c4 = (f & 15) * 4;
            float4 kv = *reinterpret_cast<const float4*>(Kb + (size_t)(kt + r) * DKK + c4);
            kv.x = __uint_as_float(f2tf(kv.x)); kv.y = __uint_as_float(f2tf(kv.y));
            kv.z = __uint_as_float(f2tf(kv.z)); kv.w = __uint_as_float(f2tf(kv.w));
            *reinterpret_cast<float4*>(&sK[r][c4]) = kv;
            float4 vv = *reinterpret_cast<const float4*>(Vb + (size_t)(kt + r) * DVV + c4);
            vv.x = __uint_as_float(f2tf(vv.x)); vv.y = __uint_as_float(f2tf(vv.y));
            vv.z = __uint_as_float(f2tf(vv.z)); vv.w = __uint_as_float(f2tf(vv.w));
            *reinterpret_cast<float4*>(&sV[r][c4]) = vv;
        }
        __syncthreads();

        float s[8][4];
        #pragma unroll
        for (int nt = 0; nt < 8; nt++)
            #pragma unroll
            for (int j = 0; j < 4; j++) s[nt][j] = 0.f;

        #pragma unroll
        for (int kk = 0; kk < 8; kk++) {
            #pragma unroll
            for (int nt = 0; nt < 8; nt++) {
                unsigned b0 = __float_as_uint(sK[nt * 8 + g][kk * 8 + t    ]);
                unsigned b1 = __float_as_uint(sK[nt * 8 + g][kk * 8 + t + 4]);
                mma_tf32(s[nt][0], s[nt][1], s[nt][2], s[nt][3],
                         qa[kk][0], qa[kk][1], qa[kk][2], qa[kk][3], b0, b1);
            }
        }

        float rmax0 = -1e30f, rmax1 = -1e30f;
        #pragma unroll
        for (int nt = 0; nt < 8; nt++) {
            rmax0 = fmaxf(rmax0, fmaxf(s[nt][0], s[nt][1]));
            rmax1 = fmaxf(rmax1, fmaxf(s[nt][2], s[nt][3]));
        }
        rmax0 = fmaxf(rmax0, __shfl_xor_sync(0xffffffffu, rmax0, 1));
        rmax0 = fmaxf(rmax0, __shfl_xor_sync(0xffffffffu, rmax0, 2));
        rmax1 = fmaxf(rmax1, __shfl_xor_sync(0xffffffffu, rmax1, 1));
        rmax1 = fmaxf(rmax1, __shfl_xor_sync(0xffffffffu, rmax1, 2));

        float nm0 = fmaxf(m0, rmax0);
        float nm1 = fmaxf(m1, rmax1);
        float al0 = exp2_fast(m0 - nm0);
        float al1 = exp2_fast(m1 - nm1);
        m0 = nm0; m1 = nm1;

        float sum0 = 0.f, sum1 = 0.f;
        #pragma unroll
        for (int nt = 0; nt < 8; nt++) {
            s[nt][0] = exp2_fast(s[nt][0] - m0);
            s[nt][1] = exp2_fast(s[nt][1] - m0);
            s[nt][2] = exp2_fast(s[nt][2] - m1);
            s[nt][3] = exp2_fast(s[nt][3] - m1);
            sum0 += s[nt][0] + s[nt][1];
            sum1 += s[nt][2] + s[nt][3];
        }
        sum0 += __shfl_xor_sync(0xffffffffu, sum0, 1);
        sum0 += __shfl_xor_sync(0xffffffffu, sum0, 2);
        sum1 += __shfl_xor_sync(0xffffffffu, sum1, 1);
        sum1 += __shfl_xor_sync(0xffffffffu, sum1, 2);

        l0 = l0 * al0 + sum0;
        l1 = l1 * al1 + sum1;

        #pragma unroll
        for (int vt = 0; vt < 8; vt++) {
            o[vt][0] *= al0; o[vt][1] *= al0;
            o[vt][2] *= al1; o[vt][3] *= al1;
        }

        const int srcA = (lane & ~3) | (t >> 1);
        const int srcB = srcA + 2;
        #pragma unroll
        for (int nt = 0; nt < 8; nt++) {
            unsigned u0 = f2tf(s[nt][0]);
            unsigned u1 = f2tf(s[nt][1]);
            unsigned u2 = f2tf(s[nt][2]);
            unsigned u3 = f2tf(s[nt][3]);
            unsigned x0 = __shfl_sync(0xffffffffu, u0, srcA);
            unsigned x1 = __shfl_sync(0xffffffffu, u1, srcA);
            unsigned pa0 = (t & 1) ? x1 : x0;
            unsigned y0 = __shfl_sync(0xffffffffu, u2, srcA);
            unsigned y1 = __shfl_sync(0xffffffffu, u3, srcA);
            unsigned pa1 = (t & 1) ? y1 : y0;
            x0 = __shfl_sync(0xffffffffu, u0, srcB);
            x1 = __shfl_sync(0xffffffffu, u1, srcB);
            unsigned pa2 = (t & 1) ? x1 : x0;
            y0 = __shfl_sync(0xffffffffu, u2, srcB);
            y1 = __shfl_sync(0xffffffffu, u3, srcB);
            unsigned pa3 = (t & 1) ? y1 : y0;

            #pragma unroll
            for (int vt = 0; vt < 8; vt++) {
                unsigned b0 = __float_as_uint(sV[nt * 8 + t    ][vt * 8 + g]);
                unsigned b1 = __float_as_uint(sV[nt * 8 + t + 4][vt * 8 + g]);
                mma_tf32(o[vt][0], o[vt][1], o[vt][2], o[vt][3],
                         pa0, pa1, pa2, pa3, b0, b1);
            }
        }
        __syncthreads();
    }

    float inv0 = 1.f / l0;
    float inv1 = 1.f / l1;
    int r0 = q0 + w * 16 + g;
    int r1 = r0 + 8;
    #pragma unroll
    for (int vt = 0; vt < 8; vt++) {
        float2 v0 = make_float2(o[vt][0] * inv0, o[vt][1] * inv0);
        float2 v1 = make_float2(o[vt][2] * inv1, o[vt][3] * inv1);
        *reinterpret_cast<float2*>(g_att + ((size_t)b * SS + r0) * (HH * DVV) + h * DVV + vt * 8 + 2 * t) = v0;
        *reinterpret_cast<float2*>(g_att + ((size_t)b * SS + r1) * (HH * DVV) + h * DVV + vt * 8 + 2 * t) = v1;
    }
}

// ---------------------------------------------------------------------------
extern "C" void kernel_launch(void* const* d_in, const int* in_sizes, int n_in,
                              void* d_out, int out_size)
{
    const float* x_q = (const float*)d_in[0];
    const float* x_k = (const float*)d_in[1];
    const float* x_v = (const float*)d_in[2];
    const float* Wq  = (const float*)d_in[3];
    const float* bq  = (const float*)d_in[4];
    const float* Wk  = (const float*)d_in[5];
    const float* bk  = (const float*)d_in[6];
    const float* Wv  = (const float*)d_in[7];
    const float* bv  = (const float*)d_in[8];
    const float* Wo  = (const float*)d_in[9];
    const float* bo  = (const float*)d_in[10];
    float* out = (float*)d_out;

    float *Qp, *Kp, *Vp, *Ap;
    cudaGetSymbolAddress((void**)&Qp, g_Q);
    cudaGetSymbolAddress((void**)&Kp, g_K);
    cudaGetSymbolAddress((void**)&Vp, g_V);
    cudaGetSymbolAddress((void**)&Ap, g_att);

    dim3 gproj(SS / 128, HH, BB);
    proj_mma_kernel<<<gproj, 256>>>(x_q, Wq, bq, Qp);
    proj_mma_kernel<<<gproj, 256>>>(x_k, Wk, bk, Kp);
    proj_mma_kernel<<<gproj, 256>>>(x_v, Wv, bv, Vp);

    dim3 gattn(SS / 128, HH, BB);
    attn_mma_kernel<<<gattn, 256>>>();

    dim3 gout((BB * SS) / 128, FILT / 64);
    out_mma_kernel<<<gout, 256>>>(Ap, Wo, bo, out);
}

// round 6
// speedup vs baseline: 1.5774x; 1.5774x over previous
#include <cuda_runtime.h>
#include <cuda_fp16.h>
#include <math.h>

// Problem dims
#define BB   4
#define SS   2048
#define FF   512
#define HH   8
#define DKK  64
#define DVV  64
#define FILT 512

// Scratch (allocation-free rule: __device__ globals)
__device__ float g_Q[BB*HH*SS*DKK];      // [b,h,s,dk]
__device__ float g_K[BB*HH*SS*DKK];
__device__ float g_V[BB*HH*SS*DVV];
__device__ float g_att[BB*SS*HH*DVV];    // [b,s,h*dv] concat layout

// ---------------------------------------------------------------------------
// helpers
// ---------------------------------------------------------------------------
// exp2 on FMA pipe (no MUFU). Input y <= 0 (may be hugely negative).
__device__ __forceinline__ float exp2_fast(float y) {
    y = fmaxf(y, -126.0f);
    float t = y + 12582912.0f;                 // round-to-nearest-int magic
    float n = t - 12582912.0f;
    float f = y - n;                            // f in [-0.5, 0.5]
    float p = 0.0013333558f;
    p = fmaf(p, f, 0.0096181291f);
    p = fmaf(p, f, 0.0555041087f);
    p = fmaf(p, f, 0.2402265070f);
    p = fmaf(p, f, 0.6931471806f);
    p = fmaf(p, f, 1.0f);
    int ni = __float_as_int(t) - 0x4B400000;
    float sc = __int_as_float((ni + 127) << 23);
    return p * sc;
}

__device__ __forceinline__ void mma_f16(float& d0, float& d1, float& d2, float& d3,
                                        unsigned a0, unsigned a1, unsigned a2, unsigned a3,
                                        unsigned b0, unsigned b1) {
    asm("mma.sync.aligned.m16n8k16.row.col.f32.f16.f16.f32 "
        "{%0,%1,%2,%3}, {%4,%5,%6,%7}, {%8,%9}, {%0,%1,%2,%3};"
        : "+f"(d0), "+f"(d1), "+f"(d2), "+f"(d3)
        : "r"(a0), "r"(a1), "r"(a2), "r"(a3), "r"(b0), "r"(b1));
}

__device__ __forceinline__ void ldsm_x4(unsigned& r0, unsigned& r1, unsigned& r2, unsigned& r3,
                                        unsigned addr) {
    asm volatile("ldmatrix.sync.aligned.m8n8.x4.shared.b16 {%0,%1,%2,%3}, [%4];"
                 : "=r"(r0), "=r"(r1), "=r"(r2), "=r"(r3) : "r"(addr));
}
__device__ __forceinline__ void ldsm_x4_trans(unsigned& r0, unsigned& r1, unsigned& r2, unsigned& r3,
                                              unsigned addr) {
    asm volatile("ldmatrix.sync.aligned.m8n8.x4.trans.shared.b16 {%0,%1,%2,%3}, [%4];"
                 : "=r"(r0), "=r"(r1), "=r"(r2), "=r"(r3) : "r"(addr));
}

__device__ __forceinline__ unsigned h2pack(float a, float b) {
    __half2 hv = __float22half2_rn(make_float2(a, b));
    return *reinterpret_cast<unsigned*>(&hv);
}

// ---------------------------------------------------------------------------
// Projection GEMM (FFMA, R2 version): out[b,h,s,:] = X[b,s,:] @ W[h,:,:] + b
// ---------------------------------------------------------------------------
__global__ __launch_bounds__(256) void proj_kernel(
    const float* __restrict__ X,    // [B,S,F]
    const float* __restrict__ W,    // [H,F,64]
    const float* __restrict__ bias, // [H,64]
    float* __restrict__ out)        // [B,H,S,64]
{
    const int b    = blockIdx.z;
    const int h    = blockIdx.y;
    const int row0 = blockIdx.x * 128;

    __shared__ float sX[128][33];
    __shared__ float sW[32][68];

    const int tid = threadIdx.x;
    const int tx  = tid & 15;
    const int ty  = tid >> 4;

    const float* Xb = X + ((size_t)b * SS + row0) * FF;
    const float* Wh = W + (size_t)h * FF * DKK;

    float acc[8][4];
    #pragma unroll
    for (int i = 0; i < 8; i++)
        #pragma unroll
        for (int j = 0; j < 4; j++) acc[i][j] = 0.f;

    for (int kt = 0; kt < FF; kt += 32) {
        #pragma unroll
        for (int p = 0; p < 4; p++) {
            int id = tid + p * 256;
            int r  = id >> 3;
            int c4 = (id & 7) * 4;
            float4 v = *reinterpret_cast<const float4*>(Xb + (size_t)r * FF + kt + c4);
            sX[r][c4 + 0] = v.x; sX[r][c4 + 1] = v.y;
            sX[r][c4 + 2] = v.z; sX[r][c4 + 3] = v.w;
        }
        #pragma unroll
        for (int p = 0; p < 2; p++) {
            int id = tid + p * 256;
            int r  = id >> 4;
            int c4 = (id & 15) * 4;
            float4 v = *reinterpret_cast<const float4*>(Wh + (size_t)(kt + r) * DKK + c4);
            sW[r][c4 + 0] = v.x; sW[r][c4 + 1] = v.y;
            sW[r][c4 + 2] = v.z; sW[r][c4 + 3] = v.w;
        }
        __syncthreads();

        #pragma unroll
        for (int kk = 0; kk < 32; kk++) {
            float a[8], w4[4];
            #pragma unroll
            for (int i = 0; i < 8; i++) a[i] = sX[ty * 8 + i][kk];
            #pragma unroll
            for (int j = 0; j < 4; j++) w4[j] = sW[kk][tx * 4 + j];
            #pragma unroll
            for (int i = 0; i < 8; i++)
                #pragma unroll
                for (int j = 0; j < 4; j++)
                    acc[i][j] = fmaf(a[i], w4[j], acc[i][j]);
        }
        __syncthreads();
    }

    float bv[4];
    #pragma unroll
    for (int j = 0; j < 4; j++) bv[j] = bias[h * DKK + tx * 4 + j];

    float* O = out + (((size_t)b * HH + h) * SS + row0) * DKK;
    #pragma unroll
    for (int i = 0; i < 8; i++) {
        int r = ty * 8 + i;
        #pragma unroll
        for (int j = 0; j < 4; j++)
            O[(size_t)r * DKK + tx * 4 + j] = acc[i][j] + bv[j];
    }
}

// ---------------------------------------------------------------------------
// Flash attention, fp16 mma.m16n8k16. 8 warps, Br=128 (16 rows/warp), Bc=64.
// K/V staged in smem as half (stride 72). ldmatrix for all B operands.
// P(C-frag) -> fp16 A-frag by direct cvt (no shuffles).
// ---------------------------------------------------------------------------
__global__ __launch_bounds__(256, 2) void attn_mma_kernel()
{
    const int b  = blockIdx.z;
    const int h  = blockIdx.y;
    const int q0 = blockIdx.x * 128;

    const int tid  = threadIdx.x;
    const int w    = tid >> 5;
    const int lane = tid & 31;
    const int g    = lane >> 2;
    const int t    = lane & 3;

    __shared__ __half sK[64][72];
    __shared__ __half sV[64][72];

    const float* Qb = g_Q + (((size_t)b * HH + h) * SS + q0 + w * 16) * DKK;
    const float* Kb = g_K + ((size_t)b * HH + h) * SS * DKK;
    const float* Vb = g_V + ((size_t)b * HH + h) * SS * DVV;

    const float QS = 0.125f * 1.4426950408889634f;  // softmax scale * log2(e)

    // Q A-fragments (fp16, scale folded): qa[kk][0..3], kk = 16-wide k-chunk
    unsigned qa[4][4];
    #pragma unroll
    for (int kk = 0; kk < 4; kk++) {
        const float* r0p = Qb + (size_t)g * DKK + kk * 16;
        const float* r1p = Qb + (size_t)(g + 8) * DKK + kk * 16;
        qa[kk][0] = h2pack(r0p[2 * t] * QS,     r0p[2 * t + 1] * QS);
        qa[kk][1] = h2pack(r1p[2 * t] * QS,     r1p[2 * t + 1] * QS);
        qa[kk][2] = h2pack(r0p[2 * t + 8] * QS, r0p[2 * t + 9] * QS);
        qa[kk][3] = h2pack(r1p[2 * t + 8] * QS, r1p[2 * t + 9] * QS);
    }

    float o[8][4];
    #pragma unroll
    for (int vt = 0; vt < 8; vt++)
        #pragma unroll
        for (int j = 0; j < 4; j++) o[vt][j] = 0.f;

    float m0 = -1e30f, m1 = -1e30f, l0 = 0.f, l1 = 0.f;

    // smem base addresses for ldmatrix
    unsigned sK_base, sV_base;
    {
        unsigned a;
        asm("{ .reg .u64 tt; cvta.to.shared.u64 tt, %1; cvt.u32.u64 %0, tt; }"
            : "=r"(a) : "l"((void*)&sK[0][0]));
        sK_base = a;
        asm("{ .reg .u64 tt; cvta.to.shared.u64 tt, %1; cvt.u32.u64 %0, tt; }"
            : "=r"(a) : "l"((void*)&sV[0][0]));
        sV_base = a;
    }

    for (int kt = 0; kt < SS; kt += 64) {
        // ---- stage K,V tiles (64x64) fp32->fp16 ----
        #pragma unroll
        for (int p = 0; p < 4; p++) {
            int f  = tid + p * 256;
            int r  = f >> 4;
            int c4 = (f & 15) * 4;
            float4 kv = *reinterpret_cast<const float4*>(Kb + (size_t)(kt + r) * DKK + c4);
            __half2 k01 = __float22half2_rn(make_float2(kv.x, kv.y));
            __half2 k23 = __float22half2_rn(make_float2(kv.z, kv.w));
            *reinterpret_cast<__half2*>(&sK[r][c4])     = k01;
            *reinterpret_cast<__half2*>(&sK[r][c4 + 2]) = k23;
            float4 vv = *reinterpret_cast<const float4*>(Vb + (size_t)(kt + r) * DVV + c4);
            __half2 v01 = __float22half2_rn(make_float2(vv.x, vv.y));
            __half2 v23 = __float22half2_rn(make_float2(vv.z, vv.w));
            *reinterpret_cast<__half2*>(&sV[r][c4])     = v01;
            *reinterpret_cast<__half2*>(&sV[r][c4 + 2]) = v23;
        }
        __syncthreads();

        // ---- S = Q @ K^T (16x64 per warp) ----
        float s[8][4];
        #pragma unroll
        for (int nt = 0; nt < 8; nt++)
            #pragma unroll
            for (int j = 0; j < 4; j++) s[nt][j] = 0.f;

        #pragma unroll
        for (int kk = 0; kk < 4; kk++) {
            #pragma unroll
            for (int ntp = 0; ntp < 4; ntp++) {
                // ldmatrix x4 (non-trans): M0,M1 = b0,b1 for nt=2ntp; M2,M3 for nt=2ntp+1
                int mrow = (2 * ntp + (lane >> 4)) * 8 + (lane & 7);
                int mcol = kk * 16 + ((lane >> 3) & 1) * 8;
                unsigned addr = sK_base + (unsigned)(mrow * 72 + mcol) * 2u;
                unsigned b0, b1, b2, b3;
                ldsm_x4(b0, b1, b2, b3, addr);
                mma_f16(s[2*ntp][0], s[2*ntp][1], s[2*ntp][2], s[2*ntp][3],
                        qa[kk][0], qa[kk][1], qa[kk][2], qa[kk][3], b0, b1);
                mma_f16(s[2*ntp+1][0], s[2*ntp+1][1], s[2*ntp+1][2], s[2*ntp+1][3],
                        qa[kk][0], qa[kk][1], qa[kk][2], qa[kk][3], b2, b3);
            }
        }

        // ---- online softmax (base-2) ----
        float rmax0 = -1e30f, rmax1 = -1e30f;
        #pragma unroll
        for (int nt = 0; nt < 8; nt++) {
            rmax0 = fmaxf(rmax0, fmaxf(s[nt][0], s[nt][1]));
            rmax1 = fmaxf(rmax1, fmaxf(s[nt][2], s[nt][3]));
        }
        rmax0 = fmaxf(rmax0, __shfl_xor_sync(0xffffffffu, rmax0, 1));
        rmax0 = fmaxf(rmax0, __shfl_xor_sync(0xffffffffu, rmax0, 2));
        rmax1 = fmaxf(rmax1, __shfl_xor_sync(0xffffffffu, rmax1, 1));
        rmax1 = fmaxf(rmax1, __shfl_xor_sync(0xffffffffu, rmax1, 2));

        float nm0 = fmaxf(m0, rmax0);
        float nm1 = fmaxf(m1, rmax1);
        float al0 = exp2_fast(m0 - nm0);
        float al1 = exp2_fast(m1 - nm1);
        m0 = nm0; m1 = nm1;

        float sum0 = 0.f, sum1 = 0.f;
        unsigned ph[8][2];   // P as fp16 A-frag halves: [nt][0]=rows g, [1]=rows g+8
        #pragma unroll
        for (int nt = 0; nt < 8; nt++) {
            float p0 = exp2_fast(s[nt][0] - m0);
            float p1 = exp2_fast(s[nt][1] - m0);
            float p2 = exp2_fast(s[nt][2] - m1);
            float p3 = exp2_fast(s[nt][3] - m1);
            sum0 += p0 + p1;
            sum1 += p2 + p3;
            ph[nt][0] = h2pack(p0, p1);
            ph[nt][1] = h2pack(p2, p3);
        }
        sum0 += __shfl_xor_sync(0xffffffffu, sum0, 1);
        sum0 += __shfl_xor_sync(0xffffffffu, sum0, 2);
        sum1 += __shfl_xor_sync(0xffffffffu, sum1, 1);
        sum1 += __shfl_xor_sync(0xffffffffu, sum1, 2);

        l0 = l0 * al0 + sum0;
        l1 = l1 * al1 + sum1;

        #pragma unroll
        for (int vt = 0; vt < 8; vt++) {
            o[vt][0] *= al0; o[vt][1] *= al0;
            o[vt][2] *= al1; o[vt][3] *= al1;
        }

        // ---- O += P @ V : 4 k-chunks x 4 vt-pairs ----
        #pragma unroll
        for (int m = 0; m < 4; m++) {
            unsigned pa0 = ph[2*m][0];
            unsigned pa1 = ph[2*m][1];
            unsigned pa2 = ph[2*m+1][0];
            unsigned pa3 = ph[2*m+1][1];
            #pragma unroll
            for (int vtp = 0; vtp < 4; vtp++) {
                // ldmatrix x4 trans on row-major V:
                // M0: rows 16m..+7  cols vtp*16..+7   -> b0 of vt=2vtp
                // M1: rows 16m+8..15 same cols        -> b1 of vt=2vtp
                // M2,M3: cols +8                      -> vt=2vtp+1
                int mrow = 16 * m + ((lane >> 3) & 1) * 8 + (lane & 7);
                int mcol = vtp * 16 + (lane >> 4) * 8;
                unsigned addr = sV_base + (unsigned)(mrow * 72 + mcol) * 2u;
                unsigned b0, b1, b2, b3;
                ldsm_x4_trans(b0, b1, b2, b3, addr);
                mma_f16(o[2*vtp][0], o[2*vtp][1], o[2*vtp][2], o[2*vtp][3],
                        pa0, pa1, pa2, pa3, b0, b1);
                mma_f16(o[2*vtp+1][0], o[2*vtp+1][1], o[2*vtp+1][2], o[2*vtp+1][3],
                        pa0, pa1, pa2, pa3, b2, b3);
            }
        }
        __syncthreads();
    }

    // ---- normalize + write concat layout [b, s, h*64 + v] ----
    float inv0 = 1.f / l0;
    float inv1 = 1.f / l1;
    int r0 = q0 + w * 16 + g;
    int r1 = r0 + 8;
    #pragma unroll
    for (int vt = 0; vt < 8; vt++) {
        float2 v0 = make_float2(o[vt][0] * inv0, o[vt][1] * inv0);
        float2 v1 = make_float2(o[vt][2] * inv1, o[vt][3] * inv1);
        *reinterpret_cast<float2*>(g_att + ((size_t)b * SS + r0) * (HH * DVV) + h * DVV + vt * 8 + 2 * t) = v0;
        *reinterpret_cast<float2*>(g_att + ((size_t)b * SS + r1) * (HH * DVV) + h * DVV + vt * 8 + 2 * t) = v1;
    }
}

// ---------------------------------------------------------------------------
// Output GEMM (FFMA, R2 version): out[M,512] = att[M,512] @ Wo[512,512] + bo
// ---------------------------------------------------------------------------
__global__ __launch_bounds__(256) void out_gemm_kernel(
    const float* __restrict__ A,
    const float* __restrict__ Wo,
    const float* __restrict__ bo,
    float* __restrict__ out)
{
    const int row0 = blockIdx.x * 128;
    const int col0 = blockIdx.y * 64;

    __shared__ float sA[128][33];
    __shared__ float sB[32][68];

    const int tid = threadIdx.x;
    const int tx  = tid & 15;
    const int ty  = tid >> 4;

    float acc[8][4];
    #pragma unroll
    for (int i = 0; i < 8; i++)
        #pragma unroll
        for (int j = 0; j < 4; j++) acc[i][j] = 0.f;

    for (int kt = 0; kt < FF; kt += 32) {
        #pragma unroll
        for (int p = 0; p < 4; p++) {
            int id = tid + p * 256;
            int r  = id >> 3;
            int c4 = (id & 7) * 4;
            float4 v = *reinterpret_cast<const float4*>(A + (size_t)(row0 + r) * FF + kt + c4);
            sA[r][c4 + 0] = v.x; sA[r][c4 + 1] = v.y;
            sA[r][c4 + 2] = v.z; sA[r][c4 + 3] = v.w;
        }
        #pragma unroll
        for (int p = 0; p < 2; p++) {
            int id = tid + p * 256;
            int r  = id >> 4;
            int c4 = (id & 15) * 4;
            float4 v = *reinterpret_cast<const float4*>(Wo + (size_t)(kt + r) * FILT + col0 + c4);
            sB[r][c4 + 0] = v.x; sB[r][c4 + 1] = v.y;
            sB[r][c4 + 2] = v.z; sB[r][c4 + 3] = v.w;
        }
        __syncthreads();

        #pragma unroll
        for (int kk = 0; kk < 32; kk++) {
            float a[8], w4[4];
            #pragma unroll
            for (int i = 0; i < 8; i++) a[i] = sA[ty * 8 + i][kk];
            #pragma unroll
            for (int j = 0; j < 4; j++) w4[j] = sB[kk][tx * 4 + j];
            #pragma unroll
            for (int i = 0; i < 8; i++)
                #pragma unroll
                for (int j = 0; j < 4; j++)
                    acc[i][j] = fmaf(a[i], w4[j], acc[i][j]);
        }
        __syncthreads();
    }

    float bv[4];
    #pragma unroll
    for (int j = 0; j < 4; j++) bv[j] = bo[col0 + tx * 4 + j];

    #pragma unroll
    for (int i = 0; i < 8; i++) {
        int r = row0 + ty * 8 + i;
        #pragma unroll
        for (int j = 0; j < 4; j++)
            out[(size_t)r * FILT + col0 + tx * 4 + j] = acc[i][j] + bv[j];
    }
}

// ---------------------------------------------------------------------------
extern "C" void kernel_launch(void* const* d_in, const int* in_sizes, int n_in,
                              void* d_out, int out_size)
{
    const float* x_q = (const float*)d_in[0];
    const float* x_k = (const float*)d_in[1];
    const float* x_v = (const float*)d_in[2];
    const float* Wq  = (const float*)d_in[3];
    const float* bq  = (const float*)d_in[4];
    const float* Wk  = (const float*)d_in[5];
    const float* bk  = (const float*)d_in[6];
    const float* Wv  = (const float*)d_in[7];
    const float* bv  = (const float*)d_in[8];
    const float* Wo  = (const float*)d_in[9];
    const float* bo  = (const float*)d_in[10];
    float* out = (float*)d_out;

    float *Qp, *Kp, *Vp, *Ap;
    cudaGetSymbolAddress((void**)&Qp, g_Q);
    cudaGetSymbolAddress((void**)&Kp, g_K);
    cudaGetSymbolAddress((void**)&Vp, g_V);
    cudaGetSymbolAddress((void**)&Ap, g_att);

    dim3 gproj(SS / 128, HH, BB);
    proj_kernel<<<gproj, 256>>>(x_q, Wq, bq, Qp);
    proj_kernel<<<gproj, 256>>>(x_k, Wk, bk, Kp);
    proj_kernel<<<gproj, 256>>>(x_v, Wv, bv, Vp);

    dim3 gattn(SS / 128, HH, BB);
    attn_mma_kernel<<<gattn, 256>>>();

    dim3 gout((BB * SS) / 128, FILT / 64);
    out_gemm_kernel<<<gout, 256>>>(Ap, Wo, bo, out);
}

// round 9
// speedup vs baseline: 2.4447x; 1.5498x over previous
#include <cuda_runtime.h>
#include <cuda_fp16.h>
#include <math.h>

// Problem dims
#define BB   4
#define SS   2048
#define FF   512
#define HH   8
#define DKK  64
#define DVV  64
#define FILT 512

// Scratch (allocation-free rule: __device__ globals) — fp16 intermediates
__device__ __half g_Qh[BB*HH*SS*DKK];    // [b,h,s,dk], softmax scale pre-folded
__device__ __half g_Kh[BB*HH*SS*DKK];
__device__ __half g_Vh[BB*HH*SS*DVV];
__device__ __half g_atth[BB*SS*HH*DVV];  // [b,s,h*dv] concat layout

// ---------------------------------------------------------------------------
// helpers
// ---------------------------------------------------------------------------
__device__ __forceinline__ float exp2_fast(float y) {
    y = fmaxf(y, -126.0f);
    float t = y + 12582912.0f;
    float n = t - 12582912.0f;
    float f = y - n;
    float p = 0.0013333558f;
    p = fmaf(p, f, 0.0096181291f);
    p = fmaf(p, f, 0.0555041087f);
    p = fmaf(p, f, 0.2402265070f);
    p = fmaf(p, f, 0.6931471806f);
    p = fmaf(p, f, 1.0f);
    int ni = __float_as_int(t) - 0x4B400000;
    float sc = __int_as_float((ni + 127) << 23);
    return p * sc;
}

__device__ __forceinline__ void mma_f16(float& d0, float& d1, float& d2, float& d3,
                                        unsigned a0, unsigned a1, unsigned a2, unsigned a3,
                                        unsigned b0, unsigned b1) {
    asm("mma.sync.aligned.m16n8k16.row.col.f32.f16.f16.f32 "
        "{%0,%1,%2,%3}, {%4,%5,%6,%7}, {%8,%9}, {%0,%1,%2,%3};"
        : "+f"(d0), "+f"(d1), "+f"(d2), "+f"(d3)
        : "r"(a0), "r"(a1), "r"(a2), "r"(a3), "r"(b0), "r"(b1));
}

__device__ __forceinline__ void ldsm_x4(unsigned& r0, unsigned& r1, unsigned& r2, unsigned& r3,
                                        unsigned addr) {
    asm volatile("ldmatrix.sync.aligned.m8n8.x4.shared.b16 {%0,%1,%2,%3}, [%4];"
                 : "=r"(r0), "=r"(r1), "=r"(r2), "=r"(r3) : "r"(addr));
}
__device__ __forceinline__ void ldsm_x4_trans(unsigned& r0, unsigned& r1, unsigned& r2, unsigned& r3,
                                              unsigned addr) {
    asm volatile("ldmatrix.sync.aligned.m8n8.x4.trans.shared.b16 {%0,%1,%2,%3}, [%4];"
                 : "=r"(r0), "=r"(r1), "=r"(r2), "=r"(r3) : "r"(addr));
}

__device__ __forceinline__ unsigned h2pack(float a, float b) {
    __half2 hv = __float22half2_rn(make_float2(a, b));
    return *reinterpret_cast<unsigned*>(&hv);
}

__device__ __forceinline__ unsigned smem_u32(const void* p) {
    return (unsigned)__cvta_generic_to_shared(p);
}

// ---------------------------------------------------------------------------
// fp16-mma projection: outh[b,h,s,:] = ((X[b,s,:] @ W[h,:,:]) + bias[h,:])*scale
// block: 128 rows x 64 cols, 8 warps (16 rows x 64 cols each), BK=64.
// ---------------------------------------------------------------------------
__global__ __launch_bounds__(256, 2) void proj_h_kernel(
    const float* __restrict__ X,    // [B,S,F]
    const float* __restrict__ W,    // [H,F,64]
    const float* __restrict__ bias, // [H,64]
    __half* __restrict__ outh,      // [B,H,S,64]
    float scale)
{
    const int b    = blockIdx.z;
    const int h    = blockIdx.y;
    const int row0 = blockIdx.x * 128;

    __shared__ __half sA[128][72];
    __shared__ __half sB[64][72];

    const int tid  = threadIdx.x;
    const int w    = tid >> 5;
    const int lane = tid & 31;
    const int g    = lane >> 2;
    const int t    = lane & 3;

    const float* Xb = X + ((size_t)b * SS + row0) * FF;
    const float* Wh = W + (size_t)h * FF * DKK;

    const unsigned sA_base = smem_u32(&sA[0][0]);
    const unsigned sB_base = smem_u32(&sB[0][0]);

    float acc[8][4];
    #pragma unroll
    for (int nt = 0; nt < 8; nt++)
        #pragma unroll
        for (int j = 0; j < 4; j++) acc[nt][j] = 0.f;

    for (int kt = 0; kt < FF; kt += 64) {
        // stage A 128x64 fp32->fp16
        #pragma unroll
        for (int p = 0; p < 8; p++) {
            int id = tid + p * 256;
            int r  = id >> 4;
            int c4 = (id & 15) * 4;
            float4 v = *reinterpret_cast<const float4*>(Xb + (size_t)r * FF + kt + c4);
            uint2 hv;
            hv.x = h2pack(v.x, v.y);
            hv.y = h2pack(v.z, v.w);
            *reinterpret_cast<uint2*>(&sA[r][c4]) = hv;
        }
        // stage B 64x64 fp32->fp16
        #pragma unroll
        for (int p = 0; p < 4; p++) {
            int id = tid + p * 256;
            int r  = id >> 4;
            int c4 = (id & 15) * 4;
            float4 v = *reinterpret_cast<const float4*>(Wh + (size_t)(kt + r) * DKK + c4);
            uint2 hv;
            hv.x = h2pack(v.x, v.y);
            hv.y = h2pack(v.z, v.w);
            *reinterpret_cast<uint2*>(&sB[r][c4]) = hv;
        }
        __syncthreads();

        #pragma unroll
        for (int kk = 0; kk < 4; kk++) {
            int arow = w * 16 + ((lane >> 3) & 1) * 8 + (lane & 7);
            int acol = kk * 16 + (lane >> 4) * 8;
            unsigned a0, a1, a2, a3;
            ldsm_x4(a0, a1, a2, a3, sA_base + (unsigned)(arow * 72 + acol) * 2u);

            #pragma unroll
            for (int ntp = 0; ntp < 4; ntp++) {
                int brow = kk * 16 + ((lane >> 3) & 1) * 8 + (lane & 7);
                int bcol = ntp * 16 + (lane >> 4) * 8;
                unsigned b0, b1, b2, b3;
                ldsm_x4_trans(b0, b1, b2, b3, sB_base + (unsigned)(brow * 72 + bcol) * 2u);
                mma_f16(acc[2*ntp][0], acc[2*ntp][1], acc[2*ntp][2], acc[2*ntp][3],
                        a0, a1, a2, a3, b0, b1);
                mma_f16(acc[2*ntp+1][0], acc[2*ntp+1][1], acc[2*ntp+1][2], acc[2*ntp+1][3],
                        a0, a1, a2, a3, b2, b3);
            }
        }
        __syncthreads();
    }

    const float* bh = bias + h * DKK;
    __half* Oh = outh + (((size_t)b * HH + h) * SS + row0) * DKK;
    int r0 = w * 16 + g;
    #pragma unroll
    for (int nt = 0; nt < 8; nt++) {
        int c = nt * 8 + 2 * t;
        float b0 = bh[c], b1 = bh[c + 1];
        unsigned v0 = h2pack((acc[nt][0] + b0) * scale, (acc[nt][1] + b1) * scale);
        unsigned v1 = h2pack((acc[nt][2] + b0) * scale, (acc[nt][3] + b1) * scale);
        *reinterpret_cast<unsigned*>(Oh + (size_t)r0 * DKK + c) = v0;
        *reinterpret_cast<unsigned*>(Oh + (size_t)(r0 + 8) * DKK + c) = v1;
    }
}

// ---------------------------------------------------------------------------
// fp16-mma output GEMM: out[M,512] = atth[M,512] @ Wo[512,512] + bo (fp32 out)
// ---------------------------------------------------------------------------
__global__ __launch_bounds__(256, 2) void out_h_kernel(
    const __half* __restrict__ A,   // [M, 512] fp16
    const float* __restrict__ Wo,   // [512, 512]
    const float* __restrict__ bo,   // [512]
    float* __restrict__ out)        // [M, 512]
{
    const int row0 = blockIdx.x * 128;
    const int col0 = blockIdx.y * 64;

    __shared__ __half sA[128][72];
    __shared__ __half sB[64][72];

    const int tid  = threadIdx.x;
    const int w    = tid >> 5;
    const int lane = tid & 31;
    const int g    = lane >> 2;
    const int t    = lane & 3;

    const unsigned sA_base = smem_u32(&sA[0][0]);
    const unsigned sB_base = smem_u32(&sB[0][0]);

    float acc[8][4];
    #pragma unroll
    for (int nt = 0; nt < 8; nt++)
        #pragma unroll
        for (int j = 0; j < 4; j++) acc[nt][j] = 0.f;

    for (int kt = 0; kt < FF; kt += 64) {
        // stage A 128x64 (already fp16): uint4 copies. 1024 uint4s -> p<4.
        #pragma unroll
        for (int p = 0; p < 4; p++) {
            int id = tid + p * 256;
            int r  = id >> 3;
            int c8 = (id & 7) * 8;
            uint4 v = *reinterpret_cast<const uint4*>(A + (size_t)(row0 + r) * FF + kt + c8);
            *reinterpret_cast<uint4*>(&sA[r][c8]) = v;
        }
        // stage B 64x64 fp32->fp16 (Wo window)
        #pragma unroll
        for (int p = 0; p < 4; p++) {
            int id = tid + p * 256;
            int r  = id >> 4;
            int c4 = (id & 15) * 4;
            float4 v = *reinterpret_cast<const float4*>(Wo + (size_t)(kt + r) * FILT + col0 + c4);
            uint2 hv;
            hv.x = h2pack(v.x, v.y);
            hv.y = h2pack(v.z, v.w);
            *reinterpret_cast<uint2*>(&sB[r][c4]) = hv;
        }
        __syncthreads();

        #pragma unroll
        for (int kk = 0; kk < 4; kk++) {
            int arow = w * 16 + ((lane >> 3) & 1) * 8 + (lane & 7);
            int acol = kk * 16 + (lane >> 4) * 8;
            unsigned a0, a1, a2, a3;
            ldsm_x4(a0, a1, a2, a3, sA_base + (unsigned)(arow * 72 + acol) * 2u);

            #pragma unroll
            for (int ntp = 0; ntp < 4; ntp++) {
                int brow = kk * 16 + ((lane >> 3) & 1) * 8 + (lane & 7);
                int bcol = ntp * 16 + (lane >> 4) * 8;
                unsigned b0, b1, b2, b3;
                ldsm_x4_trans(b0, b1, b2, b3, sB_base + (unsigned)(brow * 72 + bcol) * 2u);
                mma_f16(acc[2*ntp][0], acc[2*ntp][1], acc[2*ntp][2], acc[2*ntp][3],
                        a0, a1, a2, a3, b0, b1);
                mma_f16(acc[2*ntp+1][0], acc[2*ntp+1][1], acc[2*ntp+1][2], acc[2*ntp+1][3],
                        a0, a1, a2, a3, b2, b3);
            }
        }
        __syncthreads();
    }

    int r0 = row0 + w * 16 + g;
    #pragma unroll
    for (int nt = 0; nt < 8; nt++) {
        int c = col0 + nt * 8 + 2 * t;
        float b0 = bo[c], b1 = bo[c + 1];
        float2 v0 = make_float2(acc[nt][0] + b0, acc[nt][1] + b1);
        float2 v1 = make_float2(acc[nt][2] + b0, acc[nt][3] + b1);
        *reinterpret_cast<float2*>(out + (size_t)r0 * FILT + c) = v0;
        *reinterpret_cast<float2*>(out + (size_t)(r0 + 8) * FILT + c) = v1;
    }
}

// ---------------------------------------------------------------------------
// Flash attention, fp16 mma.m16n8k16, fp16 inputs (scale pre-folded into Q).
// 8 warps, Br=128 (16 rows/warp), Bc=64. Writes fp16 concat output.
// ---------------------------------------------------------------------------
__global__ __launch_bounds__(256, 2) void attn_mma_kernel()
{
    const int b  = blockIdx.z;
    const int h  = blockIdx.y;
    const int q0 = blockIdx.x * 128;

    const int tid  = threadIdx.x;
    const int w    = tid >> 5;
    const int lane = tid & 31;
    const int g    = lane >> 2;
    const int t    = lane & 3;

    __shared__ __half sK[64][72];
    __shared__ __half sV[64][72];

    const __half* Qb = g_Qh + (((size_t)b * HH + h) * SS + q0 + w * 16) * DKK;
    const __half* Kb = g_Kh + ((size_t)b * HH + h) * SS * DKK;
    const __half* Vb = g_Vh + ((size_t)b * HH + h) * SS * DVV;

    // Q A-fragments: direct 32-bit loads (scale folded in projection)
    unsigned qa[4][4];
    #pragma unroll
    for (int kk = 0; kk < 4; kk++) {
        const __half* r0p = Qb + (size_t)g * DKK + kk * 16;
        const __half* r1p = Qb + (size_t)(g + 8) * DKK + kk * 16;
        qa[kk][0] = *reinterpret_cast<const unsigned*>(r0p + 2 * t);
        qa[kk][1] = *reinterpret_cast<const unsigned*>(r1p + 2 * t);
        qa[kk][2] = *reinterpret_cast<const unsigned*>(r0p + 2 * t + 8);
        qa[kk][3] = *reinterpret_cast<const unsigned*>(r1p + 2 * t + 8);
    }

    float o[8][4];
    #pragma unroll
    for (int vt = 0; vt < 8; vt++)
        #pragma unroll
        for (int j = 0; j < 4; j++) o[vt][j] = 0.f;

    float m0 = -1e30f, m1 = -1e30f, l0 = 0.f, l1 = 0.f;

    const unsigned sK_base = smem_u32(&sK[0][0]);
    const unsigned sV_base = smem_u32(&sV[0][0]);

    for (int kt = 0; kt < SS; kt += 64) {
        // ---- stage K,V tiles (64x64 halves): pure uint4 copies ----
        #pragma unroll
        for (int p = 0; p < 2; p++) {
            int id = tid + p * 256;
            int r  = id >> 3;
            int c8 = (id & 7) * 8;
            uint4 kv = *reinterpret_cast<const uint4*>(Kb + (size_t)(kt + r) * DKK + c8);
            *reinterpret_cast<uint4*>(&sK[r][c8]) = kv;
            uint4 vv = *reinterpret_cast<const uint4*>(Vb + (size_t)(kt + r) * DVV + c8);
            *reinterpret_cast<uint4*>(&sV[r][c8]) = vv;
        }
        __syncthreads();

        // ---- S = Q @ K^T (16x64 per warp) ----
        float s[8][4];
        #pragma unroll
        for (int nt = 0; nt < 8; nt++)
            #pragma unroll
            for (int j = 0; j < 4; j++) s[nt][j] = 0.f;

        #pragma unroll
        for (int kk = 0; kk < 4; kk++) {
            #pragma unroll
            for (int ntp = 0; ntp < 4; ntp++) {
                int mrow = (2 * ntp + (lane >> 4)) * 8 + (lane & 7);
                int mcol = kk * 16 + ((lane >> 3) & 1) * 8;
                unsigned addr = sK_base + (unsigned)(mrow * 72 + mcol) * 2u;
                unsigned b0, b1, b2, b3;
                ldsm_x4(b0, b1, b2, b3, addr);
                mma_f16(s[2*ntp][0], s[2*ntp][1], s[2*ntp][2], s[2*ntp][3],
                        qa[kk][0], qa[kk][1], qa[kk][2], qa[kk][3], b0, b1);
                mma_f16(s[2*ntp+1][0], s[2*ntp+1][1], s[2*ntp+1][2], s[2*ntp+1][3],
                        qa[kk][0], qa[kk][1], qa[kk][2], qa[kk][3], b2, b3);
            }
        }

        // ---- online softmax (base-2) ----
        float rmax0 = -1e30f, rmax1 = -1e30f;
        #pragma unroll
        for (int nt = 0; nt < 8; nt++) {
            rmax0 = fmaxf(rmax0, fmaxf(s[nt][0], s[nt][1]));
            rmax1 = fmaxf(rmax1, fmaxf(s[nt][2], s[nt][3]));
        }
        rmax0 = fmaxf(rmax0, __shfl_xor_sync(0xffffffffu, rmax0, 1));
        rmax0 = fmaxf(rmax0, __shfl_xor_sync(0xffffffffu, rmax0, 2));
        rmax1 = fmaxf(rmax1, __shfl_xor_sync(0xffffffffu, rmax1, 1));
        rmax1 = fmaxf(rmax1, __shfl_xor_sync(0xffffffffu, rmax1, 2));

        float nm0 = fmaxf(m0, rmax0);
        float nm1 = fmaxf(m1, rmax1);
        float al0 = exp2_fast(m0 - nm0);
        float al1 = exp2_fast(m1 - nm1);
        m0 = nm0; m1 = nm1;

        float sum0 = 0.f, sum1 = 0.f;
        unsigned ph[8][2];
        #pragma unroll
        for (int nt = 0; nt < 8; nt++) {
            float p0 = exp2_fast(s[nt][0] - m0);
            float p1 = exp2_fast(s[nt][1] - m0);
            float p2 = exp2_fast(s[nt][2] - m1);
            float p3 = exp2_fast(s[nt][3] - m1);
            sum0 += p0 + p1;
            sum1 += p2 + p3;
            ph[nt][0] = h2pack(p0, p1);
            ph[nt][1] = h2pack(p2, p3);
        }
        sum0 += __shfl_xor_sync(0xffffffffu, sum0, 1);
        sum0 += __shfl_xor_sync(0xffffffffu, sum0, 2);
        sum1 += __shfl_xor_sync(0xffffffffu, sum1, 1);
        sum1 += __shfl_xor_sync(0xffffffffu, sum1, 2);

        l0 = l0 * al0 + sum0;
        l1 = l1 * al1 + sum1;

        #pragma unroll
        for (int vt = 0; vt < 8; vt++) {
            o[vt][0] *= al0; o[vt][1] *= al0;
            o[vt][2] *= al1; o[vt][3] *= al1;
        }

        // ---- O += P @ V ----
        #pragma unroll
        for (int m = 0; m < 4; m++) {
            unsigned pa0 = ph[2*m][0];
            unsigned pa1 = ph[2*m][1];
            unsigned pa2 = ph[2*m+1][0];
            unsigned pa3 = ph[2*m+1][1];
            #pragma unroll
            for (int vtp = 0; vtp < 4; vtp++) {
                int mrow = 16 * m + ((lane >> 3) & 1) * 8 + (lane & 7);
                int mcol = vtp * 16 + (lane >> 4) * 8;
                unsigned addr = sV_base + (unsigned)(mrow * 72 + mcol) * 2u;
                unsigned b0, b1, b2, b3;
                ldsm_x4_trans(b0, b1, b2, b3, addr);
                mma_f16(o[2*vtp][0], o[2*vtp][1], o[2*vtp][2], o[2*vtp][3],
                        pa0, pa1, pa2, pa3, b0, b1);
                mma_f16(o[2*vtp+1][0], o[2*vtp+1][1], o[2*vtp+1][2], o[2*vtp+1][3],
                        pa0, pa1, pa2, pa3, b2, b3);
            }
        }
        __syncthreads();
    }

    // ---- normalize + write fp16 concat layout [b, s, h*64 + v] ----
    float inv0 = 1.f / l0;
    float inv1 = 1.f / l1;
    int r0 = q0 + w * 16 + g;
    int r1 = r0 + 8;
    #pragma unroll
    for (int vt = 0; vt < 8; vt++) {
        unsigned v0 = h2pack(o[vt][0] * inv0, o[vt][1] * inv0);
        unsigned v1 = h2pack(o[vt][2] * inv1, o[vt][3] * inv1);
        *reinterpret_cast<unsigned*>(g_atth + ((size_t)b * SS + r0) * (HH * DVV) + h * DVV + vt * 8 + 2 * t) = v0;
        *reinterpret_cast<unsigned*>(g_atth + ((size_t)b * SS + r1) * (HH * DVV) + h * DVV + vt * 8 + 2 * t) = v1;
    }
}

// ---------------------------------------------------------------------------
extern "C" void kernel_launch(void* const* d_in, const int* in_sizes, int n_in,
                              void* d_out, int out_size)
{
    const float* x_q = (const float*)d_in[0];
    const float* x_k = (const float*)d_in[1];
    const float* x_v = (const float*)d_in[2];
    const float* Wq  = (const float*)d_in[3];
    const float* bq  = (const float*)d_in[4];
    const float* Wk  = (const float*)d_in[5];
    const float* bk  = (const float*)d_in[6];
    const float* Wv  = (const float*)d_in[7];
    const float* bv  = (const float*)d_in[8];
    const float* Wo  = (const float*)d_in[9];
    const float* bo  = (const float*)d_in[10];
    float* out = (float*)d_out;

    __half *Qp, *Kp, *Vp, *Ap;
    cudaGetSymbolAddress((void**)&Qp, g_Qh);
    cudaGetSymbolAddress((void**)&Kp, g_Kh);
    cudaGetSymbolAddress((void**)&Vp, g_Vh);
    cudaGetSymbolAddress((void**)&Ap, g_atth);

    const float QS = 0.125f * 1.4426950408889634f;  // 1/sqrt(dk) * log2(e)

    dim3 gproj(SS / 128, HH, BB);
    proj_h_kernel<<<gproj, 256>>>(x_q, Wq, bq, Qp, QS);
    proj_h_kernel<<<gproj, 256>>>(x_k, Wk, bk, Kp, 1.0f);
    proj_h_kernel<<<gproj, 256>>>(x_v, Wv, bv, Vp, 1.0f);

    dim3 gattn(SS / 128, HH, BB);
    attn_mma_kernel<<<gattn, 256>>>();

    dim3 gout((BB * SS) / 128, FILT / 64);
    out_h_kernel<<<gout, 256>>>(Ap, Wo, bo, out);
}

// round 10
// speedup vs baseline: 3.9840x; 1.6296x over previous
#include <cuda_runtime.h>
#include <cuda_fp16.h>
#include <math.h>

// Problem dims
#define BB   4
#define SS   2048
#define FF   512
#define HH   8
#define DKK  64
#define DVV  64
#define FILT 512

// Scratch (allocation-free rule: __device__ globals) — fp16 intermediates
__device__ __half g_Qh[BB*HH*SS*DKK];    // [b,h,s,dk], softmax scale pre-folded
__device__ __half g_Kh[BB*HH*SS*DKK];
__device__ __half g_Vh[BB*HH*SS*DVV];
__device__ __half g_atth[BB*SS*HH*DVV];  // [b,s,h*dv] concat layout

// ---------------------------------------------------------------------------
// helpers
// ---------------------------------------------------------------------------
__device__ __forceinline__ float exp2_fast(float y) {   // scalar, clamped (alpha path)
    y = fmaxf(y, -126.0f);
    float t = y + 12582912.0f;
    float n = t - 12582912.0f;
    float f = y - n;
    float p = 0.0013333558f;
    p = fmaf(p, f, 0.0096181291f);
    p = fmaf(p, f, 0.0555041087f);
    p = fmaf(p, f, 0.2402265070f);
    p = fmaf(p, f, 0.6931471806f);
    p = fmaf(p, f, 1.0f);
    int ni = __float_as_int(t) - 0x4B400000;
    float sc = __int_as_float((ni + 127) << 23);
    return p * sc;
}

// pack a float twice into a 64-bit f32x2 register
__device__ __forceinline__ unsigned long long pk2(float c) {
    unsigned long long r;
    asm("mov.b64 %0, {%1, %1};" : "=l"(r) : "f"(c));
    return r;
}

// packed exp2 of (s0 - m, s1 - m) -> fp16x2 bits. Full fp32 internal precision.
// NM = pk2(-m). No clamp: caller guarantees y in [-~20, 0].
__device__ __forceinline__ unsigned exp2_pair_ph(
    float s0, float s1, unsigned long long NM,
    unsigned long long MAG, unsigned long long NMAG, unsigned long long NEG1,
    unsigned long long C5, unsigned long long C4, unsigned long long C3,
    unsigned long long C2, unsigned long long C1, unsigned long long ONE)
{
    unsigned long long S, Y, T, N, F, P, SC, R;
    asm("mov.b64 %0, {%1, %2};" : "=l"(S) : "f"(s0), "f"(s1));
    asm("add.rn.f32x2 %0, %1, %2;" : "=l"(Y) : "l"(S), "l"(NM));    // y = s - m
    asm("add.rn.f32x2 %0, %1, %2;" : "=l"(T) : "l"(Y), "l"(MAG));   // t = y + magic
    asm("add.rn.f32x2 %0, %1, %2;" : "=l"(N) : "l"(T), "l"(NMAG));  // n = round(y)
    asm("fma.rn.f32x2 %0, %1, %2, %3;" : "=l"(F) : "l"(N), "l"(NEG1), "l"(Y)); // f = y - n
    asm("fma.rn.f32x2 %0, %1, %2, %3;" : "=l"(P) : "l"(C5), "l"(F), "l"(C4));
    asm("fma.rn.f32x2 %0, %0, %1, %2;" : "+l"(P) : "l"(F), "l"(C3));
    asm("fma.rn.f32x2 %0, %0, %1, %2;" : "+l"(P) : "l"(F), "l"(C2));
    asm("fma.rn.f32x2 %0, %0, %1, %2;" : "+l"(P) : "l"(F), "l"(C1));
    asm("fma.rn.f32x2 %0, %0, %1, %2;" : "+l"(P) : "l"(F), "l"(ONE));
    // per-lane scale 2^n from t bits: ((tbits - 0x4B400000) + 127) << 23
    unsigned t0, t1;
    asm("mov.b64 {%0, %1}, %2;" : "=r"(t0), "=r"(t1) : "l"(T));
    unsigned sc0 = (t0 - 0x4B3FFF81u) << 23;
    unsigned sc1 = (t1 - 0x4B3FFF81u) << 23;
    asm("mov.b64 %0, {%1, %2};" : "=l"(SC) : "r"(sc0), "r"(sc1));
    asm("mul.rn.f32x2 %0, %1, %2;" : "=l"(R) : "l"(P), "l"(SC));
    unsigned r0, r1, ph;
    asm("mov.b64 {%0, %1}, %2;" : "=r"(r0), "=r"(r1) : "l"(R));
    asm("cvt.rn.f16x2.f32 %0, %1, %2;"
        : "=r"(ph) : "f"(__uint_as_float(r1)), "f"(__uint_as_float(r0)));
    return ph;
}

__device__ __forceinline__ void mma_f16(float& d0, float& d1, float& d2, float& d3,
                                        unsigned a0, unsigned a1, unsigned a2, unsigned a3,
                                        unsigned b0, unsigned b1) {
    asm("mma.sync.aligned.m16n8k16.row.col.f32.f16.f16.f32 "
        "{%0,%1,%2,%3}, {%4,%5,%6,%7}, {%8,%9}, {%0,%1,%2,%3};"
        : "+f"(d0), "+f"(d1), "+f"(d2), "+f"(d3)
        : "r"(a0), "r"(a1), "r"(a2), "r"(a3), "r"(b0), "r"(b1));
}

__device__ __forceinline__ void ldsm_x4(unsigned& r0, unsigned& r1, unsigned& r2, unsigned& r3,
                                        unsigned addr) {
    asm volatile("ldmatrix.sync.aligned.m8n8.x4.shared.b16 {%0,%1,%2,%3}, [%4];"
                 : "=r"(r0), "=r"(r1), "=r"(r2), "=r"(r3) : "r"(addr));
}
__device__ __forceinline__ void ldsm_x4_trans(unsigned& r0, unsigned& r1, unsigned& r2, unsigned& r3,
                                              unsigned addr) {
    asm volatile("ldmatrix.sync.aligned.m8n8.x4.trans.shared.b16 {%0,%1,%2,%3}, [%4];"
                 : "=r"(r0), "=r"(r1), "=r"(r2), "=r"(r3) : "r"(addr));
}

__device__ __forceinline__ unsigned h2pack(float a, float b) {
    __half2 hv = __float22half2_rn(make_float2(a, b));
    return *reinterpret_cast<unsigned*>(&hv);
}

__device__ __forceinline__ unsigned smem_u32(const void* p) {
    return (unsigned)__cvta_generic_to_shared(p);
}

// ---------------------------------------------------------------------------
// fp16-mma projection: outh[b,h,s,:] = ((X[b,s,:] @ W[h,:,:]) + bias[h,:])*scale
// ---------------------------------------------------------------------------
__global__ __launch_bounds__(256, 2) void proj_h_kernel(
    const float* __restrict__ X,    // [B,S,F]
    const float* __restrict__ W,    // [H,F,64]
    const float* __restrict__ bias, // [H,64]
    __half* __restrict__ outh,      // [B,H,S,64]
    float scale)
{
    const int b    = blockIdx.z;
    const int h    = blockIdx.y;
    const int row0 = blockIdx.x * 128;

    __shared__ __half sA[128][72];
    __shared__ __half sB[64][72];

    const int tid  = threadIdx.x;
    const int w    = tid >> 5;
    const int lane = tid & 31;
    const int g    = lane >> 2;
    const int t    = lane & 3;

    const float* Xb = X + ((size_t)b * SS + row0) * FF;
    const float* Wh = W + (size_t)h * FF * DKK;

    const unsigned sA_base = smem_u32(&sA[0][0]);
    const unsigned sB_base = smem_u32(&sB[0][0]);

    float acc[8][4];
    #pragma unroll
    for (int nt = 0; nt < 8; nt++)
        #pragma unroll
        for (int j = 0; j < 4; j++) acc[nt][j] = 0.f;

    for (int kt = 0; kt < FF; kt += 64) {
        #pragma unroll
        for (int p = 0; p < 8; p++) {
            int id = tid + p * 256;
            int r  = id >> 4;
            int c4 = (id & 15) * 4;
            float4 v = *reinterpret_cast<const float4*>(Xb + (size_t)r * FF + kt + c4);
            uint2 hv;
            hv.x = h2pack(v.x, v.y);
            hv.y = h2pack(v.z, v.w);
            *reinterpret_cast<uint2*>(&sA[r][c4]) = hv;
        }
        #pragma unroll
        for (int p = 0; p < 4; p++) {
            int id = tid + p * 256;
            int r  = id >> 4;
            int c4 = (id & 15) * 4;
            float4 v = *reinterpret_cast<const float4*>(Wh + (size_t)(kt + r) * DKK + c4);
            uint2 hv;
            hv.x = h2pack(v.x, v.y);
            hv.y = h2pack(v.z, v.w);
            *reinterpret_cast<uint2*>(&sB[r][c4]) = hv;
        }
        __syncthreads();

        #pragma unroll
        for (int kk = 0; kk < 4; kk++) {
            int arow = w * 16 + ((lane >> 3) & 1) * 8 + (lane & 7);
            int acol = kk * 16 + (lane >> 4) * 8;
            unsigned a0, a1, a2, a3;
            ldsm_x4(a0, a1, a2, a3, sA_base + (unsigned)(arow * 72 + acol) * 2u);

            #pragma unroll
            for (int ntp = 0; ntp < 4; ntp++) {
                int brow = kk * 16 + ((lane >> 3) & 1) * 8 + (lane & 7);
                int bcol = ntp * 16 + (lane >> 4) * 8;
                unsigned b0, b1, b2, b3;
                ldsm_x4_trans(b0, b1, b2, b3, sB_base + (unsigned)(brow * 72 + bcol) * 2u);
                mma_f16(acc[2*ntp][0], acc[2*ntp][1], acc[2*ntp][2], acc[2*ntp][3],
                        a0, a1, a2, a3, b0, b1);
                mma_f16(acc[2*ntp+1][0], acc[2*ntp+1][1], acc[2*ntp+1][2], acc[2*ntp+1][3],
                        a0, a1, a2, a3, b2, b3);
            }
        }
        __syncthreads();
    }

    const float* bh = bias + h * DKK;
    __half* Oh = outh + (((size_t)b * HH + h) * SS + row0) * DKK;
    int r0 = w * 16 + g;
    #pragma unroll
    for (int nt = 0; nt < 8; nt++) {
        int c = nt * 8 + 2 * t;
        float b0 = bh[c], b1 = bh[c + 1];
        unsigned v0 = h2pack((acc[nt][0] + b0) * scale, (acc[nt][1] + b1) * scale);
        unsigned v1 = h2pack((acc[nt][2] + b0) * scale, (acc[nt][3] + b1) * scale);
        *reinterpret_cast<unsigned*>(Oh + (size_t)r0 * DKK + c) = v0;
        *reinterpret_cast<unsigned*>(Oh + (size_t)(r0 + 8) * DKK + c) = v1;
    }
}

// ---------------------------------------------------------------------------
// fp16-mma output GEMM: out[M,512] = atth[M,512] @ Wo[512,512] + bo (fp32 out)
// ---------------------------------------------------------------------------
__global__ __launch_bounds__(256, 2) void out_h_kernel(
    const __half* __restrict__ A,   // [M, 512] fp16
    const float* __restrict__ Wo,   // [512, 512]
    const float* __restrict__ bo,   // [512]
    float* __restrict__ out)        // [M, 512]
{
    const int row0 = blockIdx.x * 128;
    const int col0 = blockIdx.y * 64;

    __shared__ __half sA[128][72];
    __shared__ __half sB[64][72];

    const int tid  = threadIdx.x;
    const int w    = tid >> 5;
    const int lane = tid & 31;
    const int g    = lane >> 2;
    const int t    = lane & 3;

    const unsigned sA_base = smem_u32(&sA[0][0]);
    const unsigned sB_base = smem_u32(&sB[0][0]);

    float acc[8][4];
    #pragma unroll
    for (int nt = 0; nt < 8; nt++)
        #pragma unroll
        for (int j = 0; j < 4; j++) acc[nt][j] = 0.f;

    for (int kt = 0; kt < FF; kt += 64) {
        #pragma unroll
        for (int p = 0; p < 4; p++) {
            int id = tid + p * 256;
            int r  = id >> 3;
            int c8 = (id & 7) * 8;
            uint4 v = *reinterpret_cast<const uint4*>(A + (size_t)(row0 + r) * FF + kt + c8);
            *reinterpret_cast<uint4*>(&sA[r][c8]) = v;
        }
        #pragma unroll
        for (int p = 0; p < 4; p++) {
            int id = tid + p * 256;
            int r  = id >> 4;
            int c4 = (id & 15) * 4;
            float4 v = *reinterpret_cast<const float4*>(Wo + (size_t)(kt + r) * FILT + col0 + c4);
            uint2 hv;
            hv.x = h2pack(v.x, v.y);
            hv.y = h2pack(v.z, v.w);
            *reinterpret_cast<uint2*>(&sB[r][c4]) = hv;
        }
        __syncthreads();

        #pragma unroll
        for (int kk = 0; kk < 4; kk++) {
            int arow = w * 16 + ((lane >> 3) & 1) * 8 + (lane & 7);
            int acol = kk * 16 + (lane >> 4) * 8;
            unsigned a0, a1, a2, a3;
            ldsm_x4(a0, a1, a2, a3, sA_base + (unsigned)(arow * 72 + acol) * 2u);

            #pragma unroll
            for (int ntp = 0; ntp < 4; ntp++) {
                int brow = kk * 16 + ((lane >> 3) & 1) * 8 + (lane & 7);
                int bcol = ntp * 16 + (lane >> 4) * 8;
                unsigned b0, b1, b2, b3;
                ldsm_x4_trans(b0, b1, b2, b3, sB_base + (unsigned)(brow * 72 + bcol) * 2u);
                mma_f16(acc[2*ntp][0], acc[2*ntp][1], acc[2*ntp][2], acc[2*ntp][3],
                        a0, a1, a2, a3, b0, b1);
                mma_f16(acc[2*ntp+1][0], acc[2*ntp+1][1], acc[2*ntp+1][2], acc[2*ntp+1][3],
                        a0, a1, a2, a3, b2, b3);
            }
        }
        __syncthreads();
    }

    int r0 = row0 + w * 16 + g;
    #pragma unroll
    for (int nt = 0; nt < 8; nt++) {
        int c = col0 + nt * 8 + 2 * t;
        float b0 = bo[c], b1 = bo[c + 1];
        float2 v0 = make_float2(acc[nt][0] + b0, acc[nt][1] + b1);
        float2 v1 = make_float2(acc[nt][2] + b0, acc[nt][3] + b1);
        *reinterpret_cast<float2*>(out + (size_t)r0 * FILT + c) = v0;
        *reinterpret_cast<float2*>(out + (size_t)(r0 + 8) * FILT + c) = v1;
    }
}

// ---------------------------------------------------------------------------
// Flash attention, fp16 mma, f32x2 packed softmax, l via ones-column MMA.
// ---------------------------------------------------------------------------
__global__ __launch_bounds__(256, 2) void attn_mma_kernel()
{
    const int b  = blockIdx.z;
    const int h  = blockIdx.y;
    const int q0 = blockIdx.x * 128;

    const int tid  = threadIdx.x;
    const int w    = tid >> 5;
    const int lane = tid & 31;
    const int g    = lane >> 2;
    const int t    = lane & 3;

    __shared__ __half sK[64][72];
    __shared__ __half sV[64][72];

    const __half* Qb = g_Qh + (((size_t)b * HH + h) * SS + q0 + w * 16) * DKK;
    const __half* Kb = g_Kh + ((size_t)b * HH + h) * SS * DKK;
    const __half* Vb = g_Vh + ((size_t)b * HH + h) * SS * DVV;

    // packed f32x2 constants (hoisted, loop-invariant)
    const unsigned long long PK_MAG  = pk2(12582912.0f);
    const unsigned long long PK_NMAG = pk2(-12582912.0f);
    const unsigned long long PK_NEG1 = pk2(-1.0f);
    const unsigned long long PK_C5   = pk2(0.0013333558f);
    const unsigned long long PK_C4   = pk2(0.0096181291f);
    const unsigned long long PK_C3   = pk2(0.0555041087f);
    const unsigned long long PK_C2   = pk2(0.2402265070f);
    const unsigned long long PK_C1   = pk2(0.6931471806f);
    const unsigned long long PK_ONE  = pk2(1.0f);
    const unsigned ONESH = 0x3C003C00u;   // half2(1.0, 1.0)

    // Q A-fragments
    unsigned qa[4][4];
    #pragma unroll
    for (int kk = 0; kk < 4; kk++) {
        const __half* r0p = Qb + (size_t)g * DKK + kk * 16;
        const __half* r1p = Qb + (size_t)(g + 8) * DKK + kk * 16;
        qa[kk][0] = *reinterpret_cast<const unsigned*>(r0p + 2 * t);
        qa[kk][1] = *reinterpret_cast<const unsigned*>(r1p + 2 * t);
        qa[kk][2] = *reinterpret_cast<const unsigned*>(r0p + 2 * t + 8);
        qa[kk][3] = *reinterpret_cast<const unsigned*>(r1p + 2 * t + 8);
    }

    float o[8][4];
    #pragma unroll
    for (int vt = 0; vt < 8; vt++)
        #pragma unroll
        for (int j = 0; j < 4; j++) o[vt][j] = 0.f;

    float la[4] = {0.f, 0.f, 0.f, 0.f};   // l accumulator via ones-column mma
    float m0 = -1e30f, m1 = -1e30f;

    const unsigned sK_base = smem_u32(&sK[0][0]);
    const unsigned sV_base = smem_u32(&sV[0][0]);

    for (int kt = 0; kt < SS; kt += 64) {
        // ---- stage K,V tiles ----
        #pragma unroll
        for (int p = 0; p < 2; p++) {
            int id = tid + p * 256;
            int r  = id >> 3;
            int c8 = (id & 7) * 8;
            uint4 kv = *reinterpret_cast<const uint4*>(Kb + (size_t)(kt + r) * DKK + c8);
            *reinterpret_cast<uint4*>(&sK[r][c8]) = kv;
            uint4 vv = *reinterpret_cast<const uint4*>(Vb + (size_t)(kt + r) * DVV + c8);
            *reinterpret_cast<uint4*>(&sV[r][c8]) = vv;
        }
        __syncthreads();

        // ---- S = Q @ K^T ----
        float s[8][4];
        #pragma unroll
        for (int nt = 0; nt < 8; nt++)
            #pragma unroll
            for (int j = 0; j < 4; j++) s[nt][j] = 0.f;

        #pragma unroll
        for (int kk = 0; kk < 4; kk++) {
            #pragma unroll
            for (int ntp = 0; ntp < 4; ntp++) {
                int mrow = (2 * ntp + (lane >> 4)) * 8 + (lane & 7);
                int mcol = kk * 16 + ((lane >> 3) & 1) * 8;
                unsigned addr = sK_base + (unsigned)(mrow * 72 + mcol) * 2u;
                unsigned b0, b1, b2, b3;
                ldsm_x4(b0, b1, b2, b3, addr);
                mma_f16(s[2*ntp][0], s[2*ntp][1], s[2*ntp][2], s[2*ntp][3],
                        qa[kk][0], qa[kk][1], qa[kk][2], qa[kk][3], b0, b1);
                mma_f16(s[2*ntp+1][0], s[2*ntp+1][1], s[2*ntp+1][2], s[2*ntp+1][3],
                        qa[kk][0], qa[kk][1], qa[kk][2], qa[kk][3], b2, b3);
            }
        }

        // ---- online softmax (base-2), packed exp ----
        float rmax0 = -1e30f, rmax1 = -1e30f;
        #pragma unroll
        for (int nt = 0; nt < 8; nt++) {
            rmax0 = fmaxf(rmax0, fmaxf(s[nt][0], s[nt][1]));
            rmax1 = fmaxf(rmax1, fmaxf(s[nt][2], s[nt][3]));
        }
        rmax0 = fmaxf(rmax0, __shfl_xor_sync(0xffffffffu, rmax0, 1));
        rmax0 = fmaxf(rmax0, __shfl_xor_sync(0xffffffffu, rmax0, 2));
        rmax1 = fmaxf(rmax1, __shfl_xor_sync(0xffffffffu, rmax1, 1));
        rmax1 = fmaxf(rmax1, __shfl_xor_sync(0xffffffffu, rmax1, 2));

        float nm0 = fmaxf(m0, rmax0);
        float nm1 = fmaxf(m1, rmax1);
        float al0 = exp2_fast(m0 - nm0);
        float al1 = exp2_fast(m1 - nm1);
        m0 = nm0; m1 = nm1;

        const unsigned long long NM0 = pk2(-m0);
        const unsigned long long NM1 = pk2(-m1);

        unsigned ph[8][2];
        #pragma unroll
        for (int nt = 0; nt < 8; nt++) {
            ph[nt][0] = exp2_pair_ph(s[nt][0], s[nt][1], NM0,
                                     PK_MAG, PK_NMAG, PK_NEG1,
                                     PK_C5, PK_C4, PK_C3, PK_C2, PK_C1, PK_ONE);
            ph[nt][1] = exp2_pair_ph(s[nt][2], s[nt][3], NM1,
                                     PK_MAG, PK_NMAG, PK_NEG1,
                                     PK_C5, PK_C4, PK_C3, PK_C2, PK_C1, PK_ONE);
        }

        // rescale accumulators (O and l)
        #pragma unroll
        for (int vt = 0; vt < 8; vt++) {
            o[vt][0] *= al0; o[vt][1] *= al0;
            o[vt][2] *= al1; o[vt][3] *= al1;
        }
        la[0] *= al0; la[1] *= al0;
        la[2] *= al1; la[3] *= al1;

        // ---- O += P @ V, l += P @ 1 ----
        #pragma unroll
        for (int m = 0; m < 4; m++) {
            unsigned pa0 = ph[2*m][0];
            unsigned pa1 = ph[2*m][1];
            unsigned pa2 = ph[2*m+1][0];
            unsigned pa3 = ph[2*m+1][1];
            mma_f16(la[0], la[1], la[2], la[3], pa0, pa1, pa2, pa3, ONESH, ONESH);
            #pragma unroll
            for (int vtp = 0; vtp < 4; vtp++) {
                int mrow = 16 * m + ((lane >> 3) & 1) * 8 + (lane & 7);
                int mcol = vtp * 16 + (lane >> 4) * 8;
                unsigned addr = sV_base + (unsigned)(mrow * 72 + mcol) * 2u;
                unsigned b0, b1, b2, b3;
                ldsm_x4_trans(b0, b1, b2, b3, addr);
                mma_f16(o[2*vtp][0], o[2*vtp][1], o[2*vtp][2], o[2*vtp][3],
                        pa0, pa1, pa2, pa3, b0, b1);
                mma_f16(o[2*vtp+1][0], o[2*vtp+1][1], o[2*vtp+1][2], o[2*vtp+1][3],
                        pa0, pa1, pa2, pa3, b2, b3);
            }
        }
        __syncthreads();
    }

    // ---- normalize + write fp16 concat layout ----
    float inv0 = 1.f / la[0];
    float inv1 = 1.f / la[2];
    int r0 = q0 + w * 16 + g;
    int r1 = r0 + 8;
    #pragma unroll
    for (int vt = 0; vt < 8; vt++) {
        unsigned v0 = h2pack(o[vt][0] * inv0, o[vt][1] * inv0);
        unsigned v1 = h2pack(o[vt][2] * inv1, o[vt][3] * inv1);
        *reinterpret_cast<unsigned*>(g_atth + ((size_t)b * SS + r0) * (HH * DVV) + h * DVV + vt * 8 + 2 * t) = v0;
        *reinterpret_cast<unsigned*>(g_atth + ((size_t)b * SS + r1) * (HH * DVV) + h * DVV + vt * 8 + 2 * t) = v1;
    }
}

// ---------------------------------------------------------------------------
extern "C" void kernel_launch(void* const* d_in, const int* in_sizes, int n_in,
                              void* d_out, int out_size)
{
    const float* x_q = (const float*)d_in[0];
    const float* x_k = (const float*)d_in[1];
    const float* x_v = (const float*)d_in[2];
    const float* Wq  = (const float*)d_in[3];
    const float* bq  = (const float*)d_in[4];
    const float* Wk  = (const float*)d_in[5];
    const float* bk  = (const float*)d_in[6];
    const float* Wv  = (const float*)d_in[7];
    const float* bv  = (const float*)d_in[8];
    const float* Wo  = (const float*)d_in[9];
    const float* bo  = (const float*)d_in[10];
    float* out = (float*)d_out;

    __half *Qp, *Kp, *Vp, *Ap;
    cudaGetSymbolAddress((void**)&Qp, g_Qh);
    cudaGetSymbolAddress((void**)&Kp, g_Kh);
    cudaGetSymbolAddress((void**)&Vp, g_Vh);
    cudaGetSymbolAddress((void**)&Ap, g_atth);

    const float QS = 0.125f * 1.4426950408889634f;  // 1/sqrt(dk) * log2(e)

    dim3 gproj(SS / 128, HH, BB);
    proj_h_kernel<<<gproj, 256>>>(x_q, Wq, bq, Qp, QS);
    proj_h_kernel<<<gproj, 256>>>(x_k, Wk, bk, Kp, 1.0f);
    proj_h_kernel<<<gproj, 256>>>(x_v, Wv, bv, Vp, 1.0f);

    dim3 gattn(SS / 128, HH, BB);
    attn_mma_kernel<<<gattn, 256>>>();

    dim3 gout((BB * SS) / 128, FILT / 64);
    out_h_kernel<<<gout, 256>>>(Ap, Wo, bo, out);
}

// round 11
// speedup vs baseline: 4.2919x; 1.0773x over previous
#include <cuda_runtime.h>
#include <cuda_fp16.h>
#include <math.h>

// Problem dims
#define BB   4
#define SS   2048
#define FF   512
#define HH   8
#define DKK  64
#define DVV  64
#define FILT 512

// Scratch (allocation-free rule: __device__ globals) — fp16 intermediates
__device__ __half g_Qh[BB*HH*SS*DKK];    // [b,h,s,dk], softmax scale pre-folded
__device__ __half g_Kh[BB*HH*SS*DKK];
__device__ __half g_Vh[BB*HH*SS*DVV];
__device__ __half g_atth[BB*SS*HH*DVV];  // [b,s,h*dv] concat layout

// ---------------------------------------------------------------------------
// helpers
// ---------------------------------------------------------------------------
__device__ __forceinline__ float exp2_fast(float y) {   // scalar, clamped (alpha path)
    y = fmaxf(y, -126.0f);
    float t = y + 12582912.0f;
    float n = t - 12582912.0f;
    float f = y - n;
    float p = 0.0013333558f;
    p = fmaf(p, f, 0.0096181291f);
    p = fmaf(p, f, 0.0555041087f);
    p = fmaf(p, f, 0.2402265070f);
    p = fmaf(p, f, 0.6931471806f);
    p = fmaf(p, f, 1.0f);
    int ni = __float_as_int(t) - 0x4B400000;
    float sc = __int_as_float((ni + 127) << 23);
    return p * sc;
}

__device__ __forceinline__ unsigned long long pk2(float c) {
    unsigned long long r;
    asm("mov.b64 %0, {%1, %1};" : "=l"(r) : "f"(c));
    return r;
}

// packed exp2 of (s0 - m, s1 - m) -> fp16x2 bits. Full fp32 internal precision.
__device__ __forceinline__ unsigned exp2_pair_ph(
    float s0, float s1, unsigned long long NM,
    unsigned long long MAG, unsigned long long NMAG, unsigned long long NEG1,
    unsigned long long C5, unsigned long long C4, unsigned long long C3,
    unsigned long long C2, unsigned long long C1, unsigned long long ONE)
{
    unsigned long long S, Y, T, N, F, P, SC, R;
    asm("mov.b64 %0, {%1, %2};" : "=l"(S) : "f"(s0), "f"(s1));
    asm("add.rn.f32x2 %0, %1, %2;" : "=l"(Y) : "l"(S), "l"(NM));
    asm("add.rn.f32x2 %0, %1, %2;" : "=l"(T) : "l"(Y), "l"(MAG));
    asm("add.rn.f32x2 %0, %1, %2;" : "=l"(N) : "l"(T), "l"(NMAG));
    asm("fma.rn.f32x2 %0, %1, %2, %3;" : "=l"(F) : "l"(N), "l"(NEG1), "l"(Y));
    asm("fma.rn.f32x2 %0, %1, %2, %3;" : "=l"(P) : "l"(C5), "l"(F), "l"(C4));
    asm("fma.rn.f32x2 %0, %0, %1, %2;" : "+l"(P) : "l"(F), "l"(C3));
    asm("fma.rn.f32x2 %0, %0, %1, %2;" : "+l"(P) : "l"(F), "l"(C2));
    asm("fma.rn.f32x2 %0, %0, %1, %2;" : "+l"(P) : "l"(F), "l"(C1));
    asm("fma.rn.f32x2 %0, %0, %1, %2;" : "+l"(P) : "l"(F), "l"(ONE));
    unsigned t0, t1;
    asm("mov.b64 {%0, %1}, %2;" : "=r"(t0), "=r"(t1) : "l"(T));
    unsigned sc0 = (t0 - 0x4B3FFF81u) << 23;
    unsigned sc1 = (t1 - 0x4B3FFF81u) << 23;
    asm("mov.b64 %0, {%1, %2};" : "=l"(SC) : "r"(sc0), "r"(sc1));
    asm("mul.rn.f32x2 %0, %1, %2;" : "=l"(R) : "l"(P), "l"(SC));
    unsigned r0, r1, ph;
    asm("mov.b64 {%0, %1}, %2;" : "=r"(r0), "=r"(r1) : "l"(R));
    asm("cvt.rn.f16x2.f32 %0, %1, %2;"
        : "=r"(ph) : "f"(__uint_as_float(r1)), "f"(__uint_as_float(r0)));
    return ph;
}

__device__ __forceinline__ void mma_f16(float& d0, float& d1, float& d2, float& d3,
                                        unsigned a0, unsigned a1, unsigned a2, unsigned a3,
                                        unsigned b0, unsigned b1) {
    asm("mma.sync.aligned.m16n8k16.row.col.f32.f16.f16.f32 "
        "{%0,%1,%2,%3}, {%4,%5,%6,%7}, {%8,%9}, {%0,%1,%2,%3};"
        : "+f"(d0), "+f"(d1), "+f"(d2), "+f"(d3)
        : "r"(a0), "r"(a1), "r"(a2), "r"(a3), "r"(b0), "r"(b1));
}

__device__ __forceinline__ void ldsm_x4(unsigned& r0, unsigned& r1, unsigned& r2, unsigned& r3,
                                        unsigned addr) {
    asm volatile("ldmatrix.sync.aligned.m8n8.x4.shared.b16 {%0,%1,%2,%3}, [%4];"
                 : "=r"(r0), "=r"(r1), "=r"(r2), "=r"(r3) : "r"(addr));
}
__device__ __forceinline__ void ldsm_x4_trans(unsigned& r0, unsigned& r1, unsigned& r2, unsigned& r3,
                                              unsigned addr) {
    asm volatile("ldmatrix.sync.aligned.m8n8.x4.trans.shared.b16 {%0,%1,%2,%3}, [%4];"
                 : "=r"(r0), "=r"(r1), "=r"(r2), "=r"(r3) : "r"(addr));
}

__device__ __forceinline__ unsigned h2pack(float a, float b) {
    __half2 hv = __float22half2_rn(make_float2(a, b));
    return *reinterpret_cast<unsigned*>(&hv);
}

__device__ __forceinline__ unsigned smem_u32(const void* p) {
    return (unsigned)__cvta_generic_to_shared(p);
}

__device__ __forceinline__ void cp16(unsigned dst, const void* src) {
    asm volatile("cp.async.cg.shared.global [%0], [%1], 16;" :: "r"(dst), "l"(src));
}
__device__ __forceinline__ void cp_commit() { asm volatile("cp.async.commit_group;"); }
__device__ __forceinline__ void cp_wait0()  { asm volatile("cp.async.wait_group 0;"); }

// ---------------------------------------------------------------------------
// Merged fp16-mma projection (Q/K/V in one launch, m = blockIdx.y>>3):
// outh[b,h,s,:] = ((X[b,s,:] @ W[h,:,:]) + bias[h,:]) * scale
// ---------------------------------------------------------------------------
__global__ __launch_bounds__(256, 2) void proj_h3_kernel(
    const float* __restrict__ Xq, const float* __restrict__ Xk, const float* __restrict__ Xv,
    const float* __restrict__ Wq, const float* __restrict__ Wk, const float* __restrict__ Wv,
    const float* __restrict__ bq, const float* __restrict__ bk, const float* __restrict__ bv,
    __half* __restrict__ Oq, __half* __restrict__ Ok, __half* __restrict__ Ov,
    float qscale)
{
    const int b    = blockIdx.z;
    const int m    = blockIdx.y >> 3;
    const int h    = blockIdx.y & 7;
    const int row0 = blockIdx.x * 128;

    const float* X    = (m == 0) ? Xq : (m == 1) ? Xk : Xv;
    const float* W    = (m == 0) ? Wq : (m == 1) ? Wk : Wv;
    const float* bias = (m == 0) ? bq : (m == 1) ? bk : bv;
    __half* outh      = (m == 0) ? Oq : (m == 1) ? Ok : Ov;
    const float scale = (m == 0) ? qscale : 1.0f;

    __shared__ __half sA[128][72];
    __shared__ __half sB[64][72];

    const int tid  = threadIdx.x;
    const int w    = tid >> 5;
    const int lane = tid & 31;
    const int g    = lane >> 2;
    const int t    = lane & 3;

    const float* Xb = X + ((size_t)b * SS + row0) * FF;
    const float* Wh = W + (size_t)h * FF * DKK;

    const unsigned sA_base = smem_u32(&sA[0][0]);
    const unsigned sB_base = smem_u32(&sB[0][0]);

    float acc[8][4];
    #pragma unroll
    for (int nt = 0; nt < 8; nt++)
        #pragma unroll
        for (int j = 0; j < 4; j++) acc[nt][j] = 0.f;

    for (int kt = 0; kt < FF; kt += 64) {
        #pragma unroll
        for (int p = 0; p < 8; p++) {
            int id = tid + p * 256;
            int r  = id >> 4;
            int c4 = (id & 15) * 4;
            float4 v = *reinterpret_cast<const float4*>(Xb + (size_t)r * FF + kt + c4);
            uint2 hv;
            hv.x = h2pack(v.x, v.y);
            hv.y = h2pack(v.z, v.w);
            *reinterpret_cast<uint2*>(&sA[r][c4]) = hv;
        }
        #pragma unroll
        for (int p = 0; p < 4; p++) {
            int id = tid + p * 256;
            int r  = id >> 4;
            int c4 = (id & 15) * 4;
            float4 v = *reinterpret_cast<const float4*>(Wh + (size_t)(kt + r) * DKK + c4);
            uint2 hv;
            hv.x = h2pack(v.x, v.y);
            hv.y = h2pack(v.z, v.w);
            *reinterpret_cast<uint2*>(&sB[r][c4]) = hv;
        }
        __syncthreads();

        #pragma unroll
        for (int kk = 0; kk < 4; kk++) {
            int arow = w * 16 + ((lane >> 3) & 1) * 8 + (lane & 7);
            int acol = kk * 16 + (lane >> 4) * 8;
            unsigned a0, a1, a2, a3;
            ldsm_x4(a0, a1, a2, a3, sA_base + (unsigned)(arow * 72 + acol) * 2u);

            #pragma unroll
            for (int ntp = 0; ntp < 4; ntp++) {
                int brow = kk * 16 + ((lane >> 3) & 1) * 8 + (lane & 7);
                int bcol = ntp * 16 + (lane >> 4) * 8;
                unsigned b0, b1, b2, b3;
                ldsm_x4_trans(b0, b1, b2, b3, sB_base + (unsigned)(brow * 72 + bcol) * 2u);
                mma_f16(acc[2*ntp][0], acc[2*ntp][1], acc[2*ntp][2], acc[2*ntp][3],
                        a0, a1, a2, a3, b0, b1);
                mma_f16(acc[2*ntp+1][0], acc[2*ntp+1][1], acc[2*ntp+1][2], acc[2*ntp+1][3],
                        a0, a1, a2, a3, b2, b3);
            }
        }
        __syncthreads();
    }

    const float* bh = bias + h * DKK;
    __half* Oh = outh + (((size_t)b * HH + h) * SS + row0) * DKK;
    int r0 = w * 16 + g;
    #pragma unroll
    for (int nt = 0; nt < 8; nt++) {
        int c = nt * 8 + 2 * t;
        float b0 = bh[c], b1 = bh[c + 1];
        unsigned v0 = h2pack((acc[nt][0] + b0) * scale, (acc[nt][1] + b1) * scale);
        unsigned v1 = h2pack((acc[nt][2] + b0) * scale, (acc[nt][3] + b1) * scale);
        *reinterpret_cast<unsigned*>(Oh + (size_t)r0 * DKK + c) = v0;
        *reinterpret_cast<unsigned*>(Oh + (size_t)(r0 + 8) * DKK + c) = v1;
    }
}

// ---------------------------------------------------------------------------
// fp16-mma output GEMM: out[M,512] = atth[M,512] @ Wo[512,512] + bo (fp32 out)
// ---------------------------------------------------------------------------
__global__ __launch_bounds__(256, 2) void out_h_kernel(
    const __half* __restrict__ A,   // [M, 512] fp16
    const float* __restrict__ Wo,   // [512, 512]
    const float* __restrict__ bo,   // [512]
    float* __restrict__ out)        // [M, 512]
{
    const int row0 = blockIdx.x * 128;
    const int col0 = blockIdx.y * 64;

    __shared__ __half sA[128][72];
    __shared__ __half sB[64][72];

    const int tid  = threadIdx.x;
    const int w    = tid >> 5;
    const int lane = tid & 31;
    const int g    = lane >> 2;
    const int t    = lane & 3;

    const unsigned sA_base = smem_u32(&sA[0][0]);
    const unsigned sB_base = smem_u32(&sB[0][0]);

    float acc[8][4];
    #pragma unroll
    for (int nt = 0; nt < 8; nt++)
        #pragma unroll
        for (int j = 0; j < 4; j++) acc[nt][j] = 0.f;

    for (int kt = 0; kt < FF; kt += 64) {
        #pragma unroll
        for (int p = 0; p < 4; p++) {
            int id = tid + p * 256;
            int r  = id >> 3;
            int c8 = (id & 7) * 8;
            uint4 v = *reinterpret_cast<const uint4*>(A + (size_t)(row0 + r) * FF + kt + c8);
            *reinterpret_cast<uint4*>(&sA[r][c8]) = v;
        }
        #pragma unroll
        for (int p = 0; p < 4; p++) {
            int id = tid + p * 256;
            int r  = id >> 4;
            int c4 = (id & 15) * 4;
            float4 v = *reinterpret_cast<const float4*>(Wo + (size_t)(kt + r) * FILT + col0 + c4);
            uint2 hv;
            hv.x = h2pack(v.x, v.y);
            hv.y = h2pack(v.z, v.w);
            *reinterpret_cast<uint2*>(&sB[r][c4]) = hv;
        }
        __syncthreads();

        #pragma unroll
        for (int kk = 0; kk < 4; kk++) {
            int arow = w * 16 + ((lane >> 3) & 1) * 8 + (lane & 7);
            int acol = kk * 16 + (lane >> 4) * 8;
            unsigned a0, a1, a2, a3;
            ldsm_x4(a0, a1, a2, a3, sA_base + (unsigned)(arow * 72 + acol) * 2u);

            #pragma unroll
            for (int ntp = 0; ntp < 4; ntp++) {
                int brow = kk * 16 + ((lane >> 3) & 1) * 8 + (lane & 7);
                int bcol = ntp * 16 + (lane >> 4) * 8;
                unsigned b0, b1, b2, b3;
                ldsm_x4_trans(b0, b1, b2, b3, sB_base + (unsigned)(brow * 72 + bcol) * 2u);
                mma_f16(acc[2*ntp][0], acc[2*ntp][1], acc[2*ntp][2], acc[2*ntp][3],
                        a0, a1, a2, a3, b0, b1);
                mma_f16(acc[2*ntp+1][0], acc[2*ntp+1][1], acc[2*ntp+1][2], acc[2*ntp+1][3],
                        a0, a1, a2, a3, b2, b3);
            }
        }
        __syncthreads();
    }

    int r0 = row0 + w * 16 + g;
    #pragma unroll
    for (int nt = 0; nt < 8; nt++) {
        int c = col0 + nt * 8 + 2 * t;
        float b0 = bo[c], b1 = bo[c + 1];
        float2 v0 = make_float2(acc[nt][0] + b0, acc[nt][1] + b1);
        float2 v1 = make_float2(acc[nt][2] + b0, acc[nt][3] + b1);
        *reinterpret_cast<float2*>(out + (size_t)r0 * FILT + c) = v0;
        *reinterpret_cast<float2*>(out + (size_t)(r0 + 8) * FILT + c) = v1;
    }
}

// ---------------------------------------------------------------------------
// Flash attention: fp16 mma, packed f32x2 softmax, l via ones-MMA,
// cp.async double-buffered K/V tiles (one barrier per iteration).
// ---------------------------------------------------------------------------
#define KVBUF (64 * 72)          // halves per buffer per array
__global__ __launch_bounds__(256, 2) void attn_mma_kernel()
{
    const int b  = blockIdx.z;
    const int h  = blockIdx.y;
    const int q0 = blockIdx.x * 128;

    const int tid  = threadIdx.x;
    const int w    = tid >> 5;
    const int lane = tid & 31;
    const int g    = lane >> 2;
    const int t    = lane & 3;

    __shared__ __half sK[2][64][72];
    __shared__ __half sV[2][64][72];

    const __half* Qb = g_Qh + (((size_t)b * HH + h) * SS + q0 + w * 16) * DKK;
    const __half* Kb = g_Kh + ((size_t)b * HH + h) * SS * DKK;
    const __half* Vb = g_Vh + ((size_t)b * HH + h) * SS * DVV;

    const unsigned long long PK_MAG  = pk2(12582912.0f);
    const unsigned long long PK_NMAG = pk2(-12582912.0f);
    const unsigned long long PK_NEG1 = pk2(-1.0f);
    const unsigned long long PK_C5   = pk2(0.0013333558f);
    const unsigned long long PK_C4   = pk2(0.0096181291f);
    const unsigned long long PK_C3   = pk2(0.0555041087f);
    const unsigned long long PK_C2   = pk2(0.2402265070f);
    const unsigned long long PK_C1   = pk2(0.6931471806f);
    const unsigned long long PK_ONE  = pk2(1.0f);
    const unsigned ONESH = 0x3C003C00u;

    unsigned qa[4][4];
    #pragma unroll
    for (int kk = 0; kk < 4; kk++) {
        const __half* r0p = Qb + (size_t)g * DKK + kk * 16;
        const __half* r1p = Qb + (size_t)(g + 8) * DKK + kk * 16;
        qa[kk][0] = *reinterpret_cast<const unsigned*>(r0p + 2 * t);
        qa[kk][1] = *reinterpret_cast<const unsigned*>(r1p + 2 * t);
        qa[kk][2] = *reinterpret_cast<const unsigned*>(r0p + 2 * t + 8);
        qa[kk][3] = *reinterpret_cast<const unsigned*>(r1p + 2 * t + 8);
    }

    float o[8][4];
    #pragma unroll
    for (int vt = 0; vt < 8; vt++)
        #pragma unroll
        for (int j = 0; j < 4; j++) o[vt][j] = 0.f;

    float la[4] = {0.f, 0.f, 0.f, 0.f};
    float m0 = -1e30f, m1 = -1e30f;

    const unsigned sK_base = smem_u32(&sK[0][0][0]);
    const unsigned sV_base = smem_u32(&sV[0][0][0]);

    // per-thread staging offsets (2 x 16B per array per tile)
    const int r_a  = tid >> 3;           // 0..31
    const int c8_a = (tid & 7) * 8;
    const int r_b  = r_a + 32;

    // prologue: issue tile 0 into buffer 0
    {
        cp16(sK_base + (unsigned)(r_a * 72 + c8_a) * 2u, Kb + (size_t)r_a * DKK + c8_a);
        cp16(sK_base + (unsigned)(r_b * 72 + c8_a) * 2u, Kb + (size_t)r_b * DKK + c8_a);
        cp16(sV_base + (unsigned)(r_a * 72 + c8_a) * 2u, Vb + (size_t)r_a * DVV + c8_a);
        cp16(sV_base + (unsigned)(r_b * 72 + c8_a) * 2u, Vb + (size_t)r_b * DVV + c8_a);
        cp_commit();
    }

    for (int kt = 0, it = 0; kt < SS; kt += 64, it++) {
        cp_wait0();
        __syncthreads();

        // prefetch next tile into the other buffer
        if (kt + 64 < SS) {
            unsigned nb = (unsigned)((it + 1) & 1) * (KVBUF * 2u);
            const __half* Kn = Kb + (size_t)(kt + 64) * DKK;
            const __half* Vn = Vb + (size_t)(kt + 64) * DVV;
            cp16(sK_base + nb + (unsigned)(r_a * 72 + c8_a) * 2u, Kn + (size_t)r_a * DKK + c8_a);
            cp16(sK_base + nb + (unsigned)(r_b * 72 + c8_a) * 2u, Kn + (size_t)r_b * DKK + c8_a);
            cp16(sV_base + nb + (unsigned)(r_a * 72 + c8_a) * 2u, Vn + (size_t)r_a * DVV + c8_a);
            cp16(sV_base + nb + (unsigned)(r_b * 72 + c8_a) * 2u, Vn + (size_t)r_b * DVV + c8_a);
            cp_commit();
        }

        const unsigned kbase = sK_base + (unsigned)(it & 1) * (KVBUF * 2u);
        const unsigned vbase = sV_base + (unsigned)(it & 1) * (KVBUF * 2u);

        // ---- S = Q @ K^T ----
        float s[8][4];
        #pragma unroll
        for (int nt = 0; nt < 8; nt++)
            #pragma unroll
            for (int j = 0; j < 4; j++) s[nt][j] = 0.f;

        #pragma unroll
        for (int kk = 0; kk < 4; kk++) {
            #pragma unroll
            for (int ntp = 0; ntp < 4; ntp++) {
                int mrow = (2 * ntp + (lane >> 4)) * 8 + (lane & 7);
                int mcol = kk * 16 + ((lane >> 3) & 1) * 8;
                unsigned addr = kbase + (unsigned)(mrow * 72 + mcol) * 2u;
                unsigned b0, b1, b2, b3;
                ldsm_x4(b0, b1, b2, b3, addr);
                mma_f16(s[2*ntp][0], s[2*ntp][1], s[2*ntp][2], s[2*ntp][3],
                        qa[kk][0], qa[kk][1], qa[kk][2], qa[kk][3], b0, b1);
                mma_f16(s[2*ntp+1][0], s[2*ntp+1][1], s[2*ntp+1][2], s[2*ntp+1][3],
                        qa[kk][0], qa[kk][1], qa[kk][2], qa[kk][3], b2, b3);
            }
        }

        // ---- online softmax (base-2) ----
        float rmax0 = -1e30f, rmax1 = -1e30f;
        #pragma unroll
        for (int nt = 0; nt < 8; nt++) {
            rmax0 = fmaxf(rmax0, fmaxf(s[nt][0], s[nt][1]));
            rmax1 = fmaxf(rmax1, fmaxf(s[nt][2], s[nt][3]));
        }
        rmax0 = fmaxf(rmax0, __shfl_xor_sync(0xffffffffu, rmax0, 1));
        rmax0 = fmaxf(rmax0, __shfl_xor_sync(0xffffffffu, rmax0, 2));
        rmax1 = fmaxf(rmax1, __shfl_xor_sync(0xffffffffu, rmax1, 1));
        rmax1 = fmaxf(rmax1, __shfl_xor_sync(0xffffffffu, rmax1, 2));

        float nm0 = fmaxf(m0, rmax0);
        float nm1 = fmaxf(m1, rmax1);
        float al0 = exp2_fast(m0 - nm0);
        float al1 = exp2_fast(m1 - nm1);
        m0 = nm0; m1 = nm1;

        const unsigned long long NM0 = pk2(-m0);
        const unsigned long long NM1 = pk2(-m1);

        unsigned ph[8][2];
        #pragma unroll
        for (int nt = 0; nt < 8; nt++) {
            ph[nt][0] = exp2_pair_ph(s[nt][0], s[nt][1], NM0,
                                     PK_MAG, PK_NMAG, PK_NEG1,
                                     PK_C5, PK_C4, PK_C3, PK_C2, PK_C1, PK_ONE);
            ph[nt][1] = exp2_pair_ph(s[nt][2], s[nt][3], NM1,
                                     PK_MAG, PK_NMAG, PK_NEG1,
                                     PK_C5, PK_C4, PK_C3, PK_C2, PK_C1, PK_ONE);
        }

        #pragma unroll
        for (int vt = 0; vt < 8; vt++) {
            o[vt][0] *= al0; o[vt][1] *= al0;
            o[vt][2] *= al1; o[vt][3] *= al1;
        }
        la[0] *= al0; la[1] *= al0;
        la[2] *= al1; la[3] *= al1;

        // ---- O += P @ V, l += P @ 1 ----
        #pragma unroll
        for (int m = 0; m < 4; m++) {
            unsigned pa0 = ph[2*m][0];
            unsigned pa1 = ph[2*m][1];
            unsigned pa2 = ph[2*m+1][0];
            unsigned pa3 = ph[2*m+1][1];
            mma_f16(la[0], la[1], la[2], la[3], pa0, pa1, pa2, pa3, ONESH, ONESH);
            #pragma unroll
            for (int vtp = 0; vtp < 4; vtp++) {
                int mrow = 16 * m + ((lane >> 3) & 1) * 8 + (lane & 7);
                int mcol = vtp * 16 + (lane >> 4) * 8;
                unsigned addr = vbase + (unsigned)(mrow * 72 + mcol) * 2u;
                unsigned b0, b1, b2, b3;
                ldsm_x4_trans(b0, b1, b2, b3, addr);
                mma_f16(o[2*vtp][0], o[2*vtp][1], o[2*vtp][2], o[2*vtp][3],
                        pa0, pa1, pa2, pa3, b0, b1);
                mma_f16(o[2*vtp+1][0], o[2*vtp+1][1], o[2*vtp+1][2], o[2*vtp+1][3],
                        pa0, pa1, pa2, pa3, b2, b3);
            }
        }
        // no trailing sync: next iteration's top sync covers WAR on this buffer
    }

    // ---- normalize + write fp16 concat layout ----
    float inv0 = 1.f / la[0];
    float inv1 = 1.f / la[2];
    int r0 = q0 + w * 16 + g;
    int r1 = r0 + 8;
    #pragma unroll
    for (int vt = 0; vt < 8; vt++) {
        unsigned v0 = h2pack(o[vt][0] * inv0, o[vt][1] * inv0);
        unsigned v1 = h2pack(o[vt][2] * inv1, o[vt][3] * inv1);
        *reinterpret_cast<unsigned*>(g_atth + ((size_t)b * SS + r0) * (HH * DVV) + h * DVV + vt * 8 + 2 * t) = v0;
        *reinterpret_cast<unsigned*>(g_atth + ((size_t)b * SS + r1) * (HH * DVV) + h * DVV + vt * 8 + 2 * t) = v1;
    }
}

// ---------------------------------------------------------------------------
extern "C" void kernel_launch(void* const* d_in, const int* in_sizes, int n_in,
                              void* d_out, int out_size)
{
    const float* x_q = (const float*)d_in[0];
    const float* x_k = (const float*)d_in[1];
    const float* x_v = (const float*)d_in[2];
    const float* Wq  = (const float*)d_in[3];
    const float* bq  = (const float*)d_in[4];
    const float* Wk  = (const float*)d_in[5];
    const float* bk  = (const float*)d_in[6];
    const float* Wv  = (const float*)d_in[7];
    const float* bv  = (const float*)d_in[8];
    const float* Wo  = (const float*)d_in[9];
    const float* bo  = (const float*)d_in[10];
    float* out = (float*)d_out;

    __half *Qp, *Kp, *Vp, *Ap;
    cudaGetSymbolAddress((void**)&Qp, g_Qh);
    cudaGetSymbolAddress((void**)&Kp, g_Kh);
    cudaGetSymbolAddress((void**)&Vp, g_Vh);
    cudaGetSymbolAddress((void**)&Ap, g_atth);

    const float QS = 0.125f * 1.4426950408889634f;  // 1/sqrt(dk) * log2(e)

    dim3 gproj(SS / 128, 3 * HH, BB);
    proj_h3_kernel<<<gproj, 256>>>(x_q, x_k, x_v, Wq, Wk, Wv, bq, bk, bv,
                                   Qp, Kp, Vp, QS);

    dim3 gattn(SS / 128, HH, BB);
    attn_mma_kernel<<<gattn, 256>>>();

    dim3 gout((BB * SS) / 128, FILT / 64);
    out_h_kernel<<<gout, 256>>>(Ap, Wo, bo, out);
}

// round 12
// speedup vs baseline: 4.3731x; 1.0189x over previous
#include <cuda_runtime.h>
#include <cuda_fp16.h>
#include <math.h>

// Problem dims
#define BB   4
#define SS   2048
#define FF   512
#define HH   8
#define DKK  64
#define DVV  64
#define FILT 512

// Scratch (allocation-free rule: __device__ globals) — fp16 intermediates
__device__ __half g_Qh[BB*HH*SS*DKK];
__device__ __half g_Kh[BB*HH*SS*DKK];
__device__ __half g_Vh[BB*HH*SS*DVV];
__device__ __half g_atth[BB*SS*HH*DVV];
// fp16 copies of inputs (converted once per call)
__device__ __half g_Xqh[BB*SS*FF];
__device__ __half g_Xkh[BB*SS*FF];
__device__ __half g_Xvh[BB*SS*FF];
__device__ __half g_Wqh[HH*FF*DKK];
__device__ __half g_Wkh[HH*FF*DKK];
__device__ __half g_Wvh[HH*FF*DVV];
__device__ __half g_Woh[FF*FILT];

// ---------------------------------------------------------------------------
// helpers
// ---------------------------------------------------------------------------
__device__ __forceinline__ float exp2_fast(float y) {
    y = fmaxf(y, -126.0f);
    float t = y + 12582912.0f;
    float n = t - 12582912.0f;
    float f = y - n;
    float p = 0.0013333558f;
    p = fmaf(p, f, 0.0096181291f);
    p = fmaf(p, f, 0.0555041087f);
    p = fmaf(p, f, 0.2402265070f);
    p = fmaf(p, f, 0.6931471806f);
    p = fmaf(p, f, 1.0f);
    int ni = __float_as_int(t) - 0x4B400000;
    float sc = __int_as_float((ni + 127) << 23);
    return p * sc;
}

__device__ __forceinline__ unsigned long long pk2(float c) {
    unsigned long long r;
    asm("mov.b64 %0, {%1, %1};" : "=l"(r) : "f"(c));
    return r;
}

__device__ __forceinline__ unsigned exp2_pair_ph(
    float s0, float s1, unsigned long long NM,
    unsigned long long MAG, unsigned long long NMAG, unsigned long long NEG1,
    unsigned long long C5, unsigned long long C4, unsigned long long C3,
    unsigned long long C2, unsigned long long C1, unsigned long long ONE)
{
    unsigned long long S, Y, T, N, F, P, SC, R;
    asm("mov.b64 %0, {%1, %2};" : "=l"(S) : "f"(s0), "f"(s1));
    asm("add.rn.f32x2 %0, %1, %2;" : "=l"(Y) : "l"(S), "l"(NM));
    asm("add.rn.f32x2 %0, %1, %2;" : "=l"(T) : "l"(Y), "l"(MAG));
    asm("add.rn.f32x2 %0, %1, %2;" : "=l"(N) : "l"(T), "l"(NMAG));
    asm("fma.rn.f32x2 %0, %1, %2, %3;" : "=l"(F) : "l"(N), "l"(NEG1), "l"(Y));
    asm("fma.rn.f32x2 %0, %1, %2, %3;" : "=l"(P) : "l"(C5), "l"(F), "l"(C4));
    asm("fma.rn.f32x2 %0, %0, %1, %2;" : "+l"(P) : "l"(F), "l"(C3));
    asm("fma.rn.f32x2 %0, %0, %1, %2;" : "+l"(P) : "l"(F), "l"(C2));
    asm("fma.rn.f32x2 %0, %0, %1, %2;" : "+l"(P) : "l"(F), "l"(C1));
    asm("fma.rn.f32x2 %0, %0, %1, %2;" : "+l"(P) : "l"(F), "l"(ONE));
    unsigned t0, t1;
    asm("mov.b64 {%0, %1}, %2;" : "=r"(t0), "=r"(t1) : "l"(T));
    unsigned sc0 = (t0 - 0x4B3FFF81u) << 23;
    unsigned sc1 = (t1 - 0x4B3FFF81u) << 23;
    asm("mov.b64 %0, {%1, %2};" : "=l"(SC) : "r"(sc0), "r"(sc1));
    asm("mul.rn.f32x2 %0, %1, %2;" : "=l"(R) : "l"(P), "l"(SC));
    unsigned r0, r1, ph;
    asm("mov.b64 {%0, %1}, %2;" : "=r"(r0), "=r"(r1) : "l"(R));
    asm("cvt.rn.f16x2.f32 %0, %1, %2;"
        : "=r"(ph) : "f"(__uint_as_float(r1)), "f"(__uint_as_float(r0)));
    return ph;
}

__device__ __forceinline__ void mma_f16(float& d0, float& d1, float& d2, float& d3,
                                        unsigned a0, unsigned a1, unsigned a2, unsigned a3,
                                        unsigned b0, unsigned b1) {
    asm("mma.sync.aligned.m16n8k16.row.col.f32.f16.f16.f32 "
        "{%0,%1,%2,%3}, {%4,%5,%6,%7}, {%8,%9}, {%0,%1,%2,%3};"
        : "+f"(d0), "+f"(d1), "+f"(d2), "+f"(d3)
        : "r"(a0), "r"(a1), "r"(a2), "r"(a3), "r"(b0), "r"(b1));
}

__device__ __forceinline__ void ldsm_x4(unsigned& r0, unsigned& r1, unsigned& r2, unsigned& r3,
                                        unsigned addr) {
    asm volatile("ldmatrix.sync.aligned.m8n8.x4.shared.b16 {%0,%1,%2,%3}, [%4];"
                 : "=r"(r0), "=r"(r1), "=r"(r2), "=r"(r3) : "r"(addr));
}
__device__ __forceinline__ void ldsm_x4_trans(unsigned& r0, unsigned& r1, unsigned& r2, unsigned& r3,
                                              unsigned addr) {
    asm volatile("ldmatrix.sync.aligned.m8n8.x4.trans.shared.b16 {%0,%1,%2,%3}, [%4];"
                 : "=r"(r0), "=r"(r1), "=r"(r2), "=r"(r3) : "r"(addr));
}

__device__ __forceinline__ unsigned h2pack(float a, float b) {
    __half2 hv = __float22half2_rn(make_float2(a, b));
    return *reinterpret_cast<unsigned*>(&hv);
}

__device__ __forceinline__ unsigned smem_u32(const void* p) {
    return (unsigned)__cvta_generic_to_shared(p);
}

__device__ __forceinline__ void cp16(unsigned dst, const void* src) {
    asm volatile("cp.async.cg.shared.global [%0], [%1], 16;" :: "r"(dst), "l"(src));
}
__device__ __forceinline__ void cp_commit() { asm volatile("cp.async.commit_group;"); }
__device__ __forceinline__ void cp_wait0()  { asm volatile("cp.async.wait_group 0;"); }

// ---------------------------------------------------------------------------
// One-shot fp32->fp16 conversion of all inputs. grid.y selects the array.
// ---------------------------------------------------------------------------
__global__ __launch_bounds__(256) void cvt_kernel(
    const float* __restrict__ xq, const float* __restrict__ xk, const float* __restrict__ xv,
    const float* __restrict__ wq, const float* __restrict__ wk, const float* __restrict__ wv,
    const float* __restrict__ wo,
    __half* __restrict__ dxq, __half* __restrict__ dxk, __half* __restrict__ dxv,
    __half* __restrict__ dwq, __half* __restrict__ dwk, __half* __restrict__ dwv,
    __half* __restrict__ dwo)
{
    const int a = blockIdx.y;
    const float* src; __half* dst; int n;
    switch (a) {
        case 0: src = xq; dst = dxq; n = BB*SS*FF;   break;
        case 1: src = xk; dst = dxk; n = BB*SS*FF;   break;
        case 2: src = xv; dst = dxv; n = BB*SS*FF;   break;
        case 3: src = wq; dst = dwq; n = HH*FF*DKK;  break;
        case 4: src = wk; dst = dwk; n = HH*FF*DKK;  break;
        case 5: src = wv; dst = dwv; n = HH*FF*DVV;  break;
        default: src = wo; dst = dwo; n = FF*FILT;   break;
    }
    int i = (blockIdx.x * 256 + threadIdx.x) * 4;
    if (i < n) {
        float4 v = *reinterpret_cast<const float4*>(src + i);
        uint2 hv;
        hv.x = h2pack(v.x, v.y);
        hv.y = h2pack(v.z, v.w);
        *reinterpret_cast<uint2*>(dst + i) = hv;
    }
}

// ---------------------------------------------------------------------------
// Shared GEMM mainloop: 128x64 tile, BK=64, cp.async double-buffered fp16.
// dyn smem layout: A[2][128][72], then B[2][64][72] (halves).
// ---------------------------------------------------------------------------
#define ABYTES (128 * 72 * 2)
#define BBYTES (64 * 72 * 2)
#define GEMM_SMEM (2 * ABYTES + 2 * BBYTES)

__device__ __forceinline__ void gemm_mainloop_h(
    const __half* __restrict__ Abase, int lda,   // A rows at Abase, stride lda
    const __half* __restrict__ Bbase, int ldb,   // B rows (k-major), window already offset
    float acc[8][4], unsigned smem_base, int tid)
{
    const int lane = tid & 31;
    const int w    = tid >> 5;
    const unsigned sA_base = smem_base;
    const unsigned sB_base = smem_base + 2 * ABYTES;

    const int ra  = tid >> 2;            // 0..63 (A: 2 chunks at rows ra, ra+64)
    const int ca  = (tid & 3) * 16;      // halves (A row = 64 halves = 4 chunks of 8)
    const int rb  = tid >> 3;            // 0..31 (B: rows rb, rb+32)
    const int cb  = (tid & 7) * 8;

    // prologue: tile 0 -> buffer 0
    {
        cp16(sA_base + (unsigned)(ra * 72 + ca) * 2u,        Abase + (size_t)ra * lda + ca);
        cp16(sA_base + (unsigned)(ra * 72 + ca + 8) * 2u,    Abase + (size_t)ra * lda + ca + 8);
        cp16(sA_base + (unsigned)((ra + 64) * 72 + ca) * 2u,     Abase + (size_t)(ra + 64) * lda + ca);
        cp16(sA_base + (unsigned)((ra + 64) * 72 + ca + 8) * 2u, Abase + (size_t)(ra + 64) * lda + ca + 8);
        cp16(sB_base + (unsigned)(rb * 72 + cb) * 2u,        Bbase + (size_t)rb * ldb + cb);
        cp16(sB_base + (unsigned)((rb + 32) * 72 + cb) * 2u, Bbase + (size_t)(rb + 32) * ldb + cb);
        cp_commit();
    }

    for (int kt = 0, it = 0; kt < FF; kt += 64, it++) {
        cp_wait0();
        __syncthreads();

        if (kt + 64 < FF) {
            unsigned ao = (unsigned)((it + 1) & 1) * ABYTES;
            unsigned bo = (unsigned)((it + 1) & 1) * BBYTES;
            const __half* An = Abase + kt + 64;
            const __half* Bn = Bbase + (size_t)(kt + 64) * ldb;
            cp16(sA_base + ao + (unsigned)(ra * 72 + ca) * 2u,        An + (size_t)ra * lda + ca);
            cp16(sA_base + ao + (unsigned)(ra * 72 + ca + 8) * 2u,    An + (size_t)ra * lda + ca + 8);
            cp16(sA_base + ao + (unsigned)((ra + 64) * 72 + ca) * 2u,     An + (size_t)(ra + 64) * lda + ca);
            cp16(sA_base + ao + (unsigned)((ra + 64) * 72 + ca + 8) * 2u, An + (size_t)(ra + 64) * lda + ca + 8);
            cp16(sB_base + bo + (unsigned)(rb * 72 + cb) * 2u,        Bn + (size_t)rb * ldb + cb);
            cp16(sB_base + bo + (unsigned)((rb + 32) * 72 + cb) * 2u, Bn + (size_t)(rb + 32) * ldb + cb);
            cp_commit();
        }

        const unsigned abase = sA_base + (unsigned)(it & 1) * ABYTES;
        const unsigned bbase = sB_base + (unsigned)(it & 1) * BBYTES;

        #pragma unroll
        for (int kk = 0; kk < 4; kk++) {
            int arow = w * 16 + ((lane >> 3) & 1) * 8 + (lane & 7);
            int acol = kk * 16 + (lane >> 4) * 8;
            unsigned a0, a1, a2, a3;
            ldsm_x4(a0, a1, a2, a3, abase + (unsigned)(arow * 72 + acol) * 2u);

            #pragma unroll
            for (int ntp = 0; ntp < 4; ntp++) {
                int brow = kk * 16 + ((lane >> 3) & 1) * 8 + (lane & 7);
                int bcol = ntp * 16 + (lane >> 4) * 8;
                unsigned b0, b1, b2, b3;
                ldsm_x4_trans(b0, b1, b2, b3, bbase + (unsigned)(brow * 72 + bcol) * 2u);
                mma_f16(acc[2*ntp][0], acc[2*ntp][1], acc[2*ntp][2], acc[2*ntp][3],
                        a0, a1, a2, a3, b0, b1);
                mma_f16(acc[2*ntp+1][0], acc[2*ntp+1][1], acc[2*ntp+1][2], acc[2*ntp+1][3],
                        a0, a1, a2, a3, b2, b3);
            }
        }
        // no trailing sync: next iteration's top sync covers the WAR
    }
}

// ---------------------------------------------------------------------------
// Merged projection (Q/K/V), fp16 in/out, pipelined mainloop.
// ---------------------------------------------------------------------------
__global__ __launch_bounds__(256, 2) void proj_h3_kernel(
    const float* __restrict__ bq, const float* __restrict__ bk, const float* __restrict__ bv,
    float qscale)
{
    extern __shared__ __half smdyn[];
    const int b    = blockIdx.z;
    const int m    = blockIdx.y >> 3;
    const int h    = blockIdx.y & 7;
    const int row0 = blockIdx.x * 128;

    const __half* X    = (m == 0) ? g_Xqh : (m == 1) ? g_Xkh : g_Xvh;
    const __half* W    = (m == 0) ? g_Wqh : (m == 1) ? g_Wkh : g_Wvh;
    const float* bias  = (m == 0) ? bq : (m == 1) ? bk : bv;
    __half* outh       = (m == 0) ? g_Qh : (m == 1) ? g_Kh : g_Vh;
    const float scale  = (m == 0) ? qscale : 1.0f;

    const int tid  = threadIdx.x;
    const int w    = tid >> 5;
    const int lane = tid & 31;
    const int g    = lane >> 2;
    const int t    = lane & 3;

    float acc[8][4];
    #pragma unroll
    for (int nt = 0; nt < 8; nt++)
        #pragma unroll
        for (int j = 0; j < 4; j++) acc[nt][j] = 0.f;

    gemm_mainloop_h(X + ((size_t)b * SS + row0) * FF, FF,
                    W + (size_t)h * FF * DKK, DKK,
                    acc, smem_u32(smdyn), tid);

    const float* bh = bias + h * DKK;
    __half* Oh = outh + (((size_t)b * HH + h) * SS + row0) * DKK;
    int r0 = w * 16 + g;
    #pragma unroll
    for (int nt = 0; nt < 8; nt++) {
        int c = nt * 8 + 2 * t;
        float b0 = bh[c], b1 = bh[c + 1];
        unsigned v0 = h2pack((acc[nt][0] + b0) * scale, (acc[nt][1] + b1) * scale);
        unsigned v1 = h2pack((acc[nt][2] + b0) * scale, (acc[nt][3] + b1) * scale);
        *reinterpret_cast<unsigned*>(Oh + (size_t)r0 * DKK + c) = v0;
        *reinterpret_cast<unsigned*>(Oh + (size_t)(r0 + 8) * DKK + c) = v1;
    }
}

// ---------------------------------------------------------------------------
// Output GEMM, fp16 A and Wo, pipelined mainloop, fp32 out.
// ---------------------------------------------------------------------------
__global__ __launch_bounds__(256, 2) void out_h_kernel(
    const float* __restrict__ bo,
    float* __restrict__ out)
{
    extern __shared__ __half smdyn[];
    const int row0 = blockIdx.x * 128;
    const int col0 = blockIdx.y * 64;

    const int tid  = threadIdx.x;
    const int w    = tid >> 5;
    const int lane = tid & 31;
    const int g    = lane >> 2;
    const int t    = lane & 3;

    float acc[8][4];
    #pragma unroll
    for (int nt = 0; nt < 8; nt++)
        #pragma unroll
        for (int j = 0; j < 4; j++) acc[nt][j] = 0.f;

    gemm_mainloop_h(g_atth + (size_t)row0 * FF, FF,
                    g_Woh + col0, FILT,
                    acc, smem_u32(smdyn), tid);

    int r0 = row0 + w * 16 + g;
    #pragma unroll
    for (int nt = 0; nt < 8; nt++) {
        int c = col0 + nt * 8 + 2 * t;
        float b0 = bo[c], b1 = bo[c + 1];
        float2 v0 = make_float2(acc[nt][0] + b0, acc[nt][1] + b1);
        float2 v1 = make_float2(acc[nt][2] + b0, acc[nt][3] + b1);
        *reinterpret_cast<float2*>(out + (size_t)r0 * FILT + c) = v0;
        *reinterpret_cast<float2*>(out + (size_t)(r0 + 8) * FILT + c) = v1;
    }
}

// ---------------------------------------------------------------------------
// Flash attention: fp16 mma, packed f32x2 softmax, l via ones-MMA,
// cp.async double-buffered K/V tiles.
// ---------------------------------------------------------------------------
#define KVBUF (64 * 72)
__global__ __launch_bounds__(256, 2) void attn_mma_kernel()
{
    const int b  = blockIdx.z;
    const int h  = blockIdx.y;
    const int q0 = blockIdx.x * 128;

    const int tid  = threadIdx.x;
    const int w    = tid >> 5;
    const int lane = tid & 31;
    const int g    = lane >> 2;
    const int t    = lane & 3;

    __shared__ __half sK[2][64][72];
    __shared__ __half sV[2][64][72];

    const __half* Qb = g_Qh + (((size_t)b * HH + h) * SS + q0 + w * 16) * DKK;
    const __half* Kb = g_Kh + ((size_t)b * HH + h) * SS * DKK;
    const __half* Vb = g_Vh + ((size_t)b * HH + h) * SS * DVV;

    const unsigned long long PK_MAG  = pk2(12582912.0f);
    const unsigned long long PK_NMAG = pk2(-12582912.0f);
    const unsigned long long PK_NEG1 = pk2(-1.0f);
    const unsigned long long PK_C5   = pk2(0.0013333558f);
    const unsigned long long PK_C4   = pk2(0.0096181291f);
    const unsigned long long PK_C3   = pk2(0.0555041087f);
    const unsigned long long PK_C2   = pk2(0.2402265070f);
    const unsigned long long PK_C1   = pk2(0.6931471806f);
    const unsigned long long PK_ONE  = pk2(1.0f);
    const unsigned ONESH = 0x3C003C00u;

    unsigned qa[4][4];
    #pragma unroll
    for (int kk = 0; kk < 4; kk++) {
        const __half* r0p = Qb + (size_t)g * DKK + kk * 16;
        const __half* r1p = Qb + (size_t)(g + 8) * DKK + kk * 16;
        qa[kk][0] = *reinterpret_cast<const unsigned*>(r0p + 2 * t);
        qa[kk][1] = *reinterpret_cast<const unsigned*>(r1p + 2 * t);
        qa[kk][2] = *reinterpret_cast<const unsigned*>(r0p + 2 * t + 8);
        qa[kk][3] = *reinterpret_cast<const unsigned*>(r1p + 2 * t + 8);
    }

    float o[8][4];
    #pragma unroll
    for (int vt = 0; vt < 8; vt++)
        #pragma unroll
        for (int j = 0; j < 4; j++) o[vt][j] = 0.f;

    float la[4] = {0.f, 0.f, 0.f, 0.f};
    float m0 = -1e30f, m1 = -1e30f;

    const unsigned sK_base = smem_u32(&sK[0][0][0]);
    const unsigned sV_base = smem_u32(&sV[0][0][0]);

    const int r_a  = tid >> 3;
    const int c8_a = (tid & 7) * 8;
    const int r_b  = r_a + 32;

    {
        cp16(sK_base + (unsigned)(r_a * 72 + c8_a) * 2u, Kb + (size_t)r_a * DKK + c8_a);
        cp16(sK_base + (unsigned)(r_b * 72 + c8_a) * 2u, Kb + (size_t)r_b * DKK + c8_a);
        cp16(sV_base + (unsigned)(r_a * 72 + c8_a) * 2u, Vb + (size_t)r_a * DVV + c8_a);
        cp16(sV_base + (unsigned)(r_b * 72 + c8_a) * 2u, Vb + (size_t)r_b * DVV + c8_a);
        cp_commit();
    }

    for (int kt = 0, it = 0; kt < SS; kt += 64, it++) {
        cp_wait0();
        __syncthreads();

        if (kt + 64 < SS) {
            unsigned nb = (unsigned)((it + 1) & 1) * (KVBUF * 2u);
            const __half* Kn = Kb + (size_t)(kt + 64) * DKK;
            const __half* Vn = Vb + (size_t)(kt + 64) * DVV;
            cp16(sK_base + nb + (unsigned)(r_a * 72 + c8_a) * 2u, Kn + (size_t)r_a * DKK + c8_a);
            cp16(sK_base + nb + (unsigned)(r_b * 72 + c8_a) * 2u, Kn + (size_t)r_b * DKK + c8_a);
            cp16(sV_base + nb + (unsigned)(r_a * 72 + c8_a) * 2u, Vn + (size_t)r_a * DVV + c8_a);
            cp16(sV_base + nb + (unsigned)(r_b * 72 + c8_a) * 2u, Vn + (size_t)r_b * DVV + c8_a);
            cp_commit();
        }

        const unsigned kbase = sK_base + (unsigned)(it & 1) * (KVBUF * 2u);
        const unsigned vbase = sV_base + (unsigned)(it & 1) * (KVBUF * 2u);

        float s[8][4];
        #pragma unroll
        for (int nt = 0; nt < 8; nt++)
            #pragma unroll
            for (int j = 0; j < 4; j++) s[nt][j] = 0.f;

        #pragma unroll
        for (int kk = 0; kk < 4; kk++) {
            #pragma unroll
            for (int ntp = 0; ntp < 4; ntp++) {
                int mrow = (2 * ntp + (lane >> 4)) * 8 + (lane & 7);
                int mcol = kk * 16 + ((lane >> 3) & 1) * 8;
                unsigned addr = kbase + (unsigned)(mrow * 72 + mcol) * 2u;
                unsigned b0, b1, b2, b3;
                ldsm_x4(b0, b1, b2, b3, addr);
                mma_f16(s[2*ntp][0], s[2*ntp][1], s[2*ntp][2], s[2*ntp][3],
                        qa[kk][0], qa[kk][1], qa[kk][2], qa[kk][3], b0, b1);
                mma_f16(s[2*ntp+1][0], s[2*ntp+1][1], s[2*ntp+1][2], s[2*ntp+1][3],
                        qa[kk][0], qa[kk][1], qa[kk][2], qa[kk][3], b2, b3);
            }
        }

        float rmax0 = -1e30f, rmax1 = -1e30f;
        #pragma unroll
        for (int nt = 0; nt < 8; nt++) {
            rmax0 = fmaxf(rmax0, fmaxf(s[nt][0], s[nt][1]));
            rmax1 = fmaxf(rmax1, fmaxf(s[nt][2], s[nt][3]));
        }
        rmax0 = fmaxf(rmax0, __shfl_xor_sync(0xffffffffu, rmax0, 1));
        rmax0 = fmaxf(rmax0, __shfl_xor_sync(0xffffffffu, rmax0, 2));
        rmax1 = fmaxf(rmax1, __shfl_xor_sync(0xffffffffu, rmax1, 1));
        rmax1 = fmaxf(rmax1, __shfl_xor_sync(0xffffffffu, rmax1, 2));

        float nm0 = fmaxf(m0, rmax0);
        float nm1 = fmaxf(m1, rmax1);
        float al0 = exp2_fast(m0 - nm0);
        float al1 = exp2_fast(m1 - nm1);
        m0 = nm0; m1 = nm1;

        const unsigned long long NM0 = pk2(-m0);
        const unsigned long long NM1 = pk2(-m1);

        unsigned ph[8][2];
        #pragma unroll
        for (int nt = 0; nt < 8; nt++) {
            ph[nt][0] = exp2_pair_ph(s[nt][0], s[nt][1], NM0,
                                     PK_MAG, PK_NMAG, PK_NEG1,
                                     PK_C5, PK_C4, PK_C3, PK_C2, PK_C1, PK_ONE);
            ph[nt][1] = exp2_pair_ph(s[nt][2], s[nt][3], NM1,
                                     PK_MAG, PK_NMAG, PK_NEG1,
                                     PK_C5, PK_C4, PK_C3, PK_C2, PK_C1, PK_ONE);
        }

        #pragma unroll
        for (int vt = 0; vt < 8; vt++) {
            o[vt][0] *= al0; o[vt][1] *= al0;
            o[vt][2] *= al1; o[vt][3] *= al1;
        }
        la[0] *= al0; la[1] *= al0;
        la[2] *= al1; la[3] *= al1;

        #pragma unroll
        for (int m = 0; m < 4; m++) {
            unsigned pa0 = ph[2*m][0];
            unsigned pa1 = ph[2*m][1];
            unsigned pa2 = ph[2*m+1][0];
            unsigned pa3 = ph[2*m+1][1];
            mma_f16(la[0], la[1], la[2], la[3], pa0, pa1, pa2, pa3, ONESH, ONESH);
            #pragma unroll
            for (int vtp = 0; vtp < 4; vtp++) {
                int mrow = 16 * m + ((lane >> 3) & 1) * 8 + (lane & 7);
                int mcol = vtp * 16 + (lane >> 4) * 8;
                unsigned addr = vbase + (unsigned)(mrow * 72 + mcol) * 2u;
                unsigned b0, b1, b2, b3;
                ldsm_x4_trans(b0, b1, b2, b3, addr);
                mma_f16(o[2*vtp][0], o[2*vtp][1], o[2*vtp][2], o[2*vtp][3],
                        pa0, pa1, pa2, pa3, b0, b1);
                mma_f16(o[2*vtp+1][0], o[2*vtp+1][1], o[2*vtp+1][2], o[2*vtp+1][3],
                        pa0, pa1, pa2, pa3, b2, b3);
            }
        }
    }

    float inv0 = 1.f / la[0];
    float inv1 = 1.f / la[2];
    int r0 = q0 + w * 16 + g;
    int r1 = r0 + 8;
    #pragma unroll
    for (int vt = 0; vt < 8; vt++) {
        unsigned v0 = h2pack(o[vt][0] * inv0, o[vt][1] * inv0);
        unsigned v1 = h2pack(o[vt][2] * inv1, o[vt][3] * inv1);
        *reinterpret_cast<unsigned*>(g_atth + ((size_t)b * SS + r0) * (HH * DVV) + h * DVV + vt * 8 + 2 * t) = v0;
        *reinterpret_cast<unsigned*>(g_atth + ((size_t)b * SS + r1) * (HH * DVV) + h * DVV + vt * 8 + 2 * t) = v1;
    }
}

// ---------------------------------------------------------------------------
extern "C" void kernel_launch(void* const* d_in, const int* in_sizes, int n_in,
                              void* d_out, int out_size)
{
    const float* x_q = (const float*)d_in[0];
    const float* x_k = (const float*)d_in[1];
    const float* x_v = (const float*)d_in[2];
    const float* Wq  = (const float*)d_in[3];
    const float* bq  = (const float*)d_in[4];
    const float* Wk  = (const float*)d_in[5];
    const float* bk  = (const float*)d_in[6];
    const float* Wv  = (const float*)d_in[7];
    const float* bv  = (const float*)d_in[8];
    const float* Wo  = (const float*)d_in[9];
    const float* bo  = (const float*)d_in[10];
    float* out = (float*)d_out;

    __half *Xqp, *Xkp, *Xvp, *Wqp, *Wkp, *Wvp, *Wop;
    cudaGetSymbolAddress((void**)&Xqp, g_Xqh);
    cudaGetSymbolAddress((void**)&Xkp, g_Xkh);
    cudaGetSymbolAddress((void**)&Xvp, g_Xvh);
    cudaGetSymbolAddress((void**)&Wqp, g_Wqh);
    cudaGetSymbolAddress((void**)&Wkp, g_Wkh);
    cudaGetSymbolAddress((void**)&Wvp, g_Wvh);
    cudaGetSymbolAddress((void**)&Wop, g_Woh);

    static int smem_set = 0;
    if (!smem_set) {
        cudaFuncSetAttribute(proj_h3_kernel, cudaFuncAttributeMaxDynamicSharedMemorySize, GEMM_SMEM);
        cudaFuncSetAttribute(out_h_kernel,  cudaFuncAttributeMaxDynamicSharedMemorySize, GEMM_SMEM);
        smem_set = 1;
    }

    const float QS = 0.125f * 1.4426950408889634f;  // 1/sqrt(dk) * log2(e)

    // 1. convert all inputs to fp16 (one launch)
    dim3 gcvt((BB * SS * FF / 4 + 255) / 256, 7);
    cvt_kernel<<<gcvt, 256>>>(x_q, x_k, x_v, Wq, Wk, Wv, Wo,
                              Xqp, Xkp, Xvp, Wqp, Wkp, Wvp, Wop);

    // 2. merged QKV projection
    dim3 gproj(SS / 128, 3 * HH, BB);
    proj_h3_kernel<<<gproj, 256, GEMM_SMEM>>>(bq, bk, bv, QS);

    // 3. attention
    dim3 gattn(SS / 128, HH, BB);
    attn_mma_kernel<<<gattn, 256>>>();

    // 4. output GEMM
    dim3 gout((BB * SS) / 128, FILT / 64);
    out_h_kernel<<<gout, 256, GEMM_SMEM>>>(bo, out);
}